// round 14
// baseline (speedup 1.0000x reference)
#include <cuda_runtime.h>
#include <cuda_bf16.h>
#include <cuda_fp16.h>
#include <cstdint>

#define B_  2
#define T_  1024
#define S_  1024
#define NQ  16
#define NKV 4
#define HD  128

// Scratch (allocation-free rule: __device__ globals)
__device__ float g_q[B_*T_*NQ*HD];      // (B,T,NQ,HD)
__device__ float g_k[B_*S_*NKV*HD];     // (B,S,NKV,HD)
__device__ float g_v[B_*S_*NKV*HD];
__device__ float g_attn[B_*T_*NQ*HD];

// ---------------------------------------------------------------------------
// helpers
// ---------------------------------------------------------------------------
__device__ __forceinline__ void mma_bf16(float d[4], const uint32_t a[4], const uint32_t b[2]) {
    asm volatile(
        "mma.sync.aligned.m16n8k16.row.col.f32.bf16.bf16.f32 "
        "{%0,%1,%2,%3}, {%4,%5,%6,%7}, {%8,%9}, {%0,%1,%2,%3};\n"
        : "+f"(d[0]), "+f"(d[1]), "+f"(d[2]), "+f"(d[3])
        : "r"(a[0]), "r"(a[1]), "r"(a[2]), "r"(a[3]), "r"(b[0]), "r"(b[1]));
}
__device__ __forceinline__ void mma_fp16(float d[4], const uint32_t a[4], const uint32_t b[2]) {
    asm volatile(
        "mma.sync.aligned.m16n8k16.row.col.f32.f16.f16.f32 "
        "{%0,%1,%2,%3}, {%4,%5,%6,%7}, {%8,%9}, {%0,%1,%2,%3};\n"
        : "+f"(d[0]), "+f"(d[1]), "+f"(d[2]), "+f"(d[3])
        : "r"(a[0]), "r"(a[1]), "r"(a[2]), "r"(a[3]), "r"(b[0]), "r"(b[1]));
}
__device__ __forceinline__ void ldsm_x4(uint32_t r[4], uint32_t addr) {
    asm volatile("ldmatrix.sync.aligned.m8n8.x4.shared.b16 {%0,%1,%2,%3}, [%4];"
                 : "=r"(r[0]), "=r"(r[1]), "=r"(r[2]), "=r"(r[3]) : "r"(addr));
}
__device__ __forceinline__ void ldsm_x4t(uint32_t r[4], uint32_t addr) {
    asm volatile("ldmatrix.sync.aligned.m8n8.x4.trans.shared.b16 {%0,%1,%2,%3}, [%4];"
                 : "=r"(r[0]), "=r"(r[1]), "=r"(r[2]), "=r"(r[3]) : "r"(addr));
}
__device__ __forceinline__ void ldsm_x2t(uint32_t r[2], uint32_t addr) {
    asm volatile("ldmatrix.sync.aligned.m8n8.x2.trans.shared.b16 {%0,%1}, [%2];"
                 : "=r"(r[0]), "=r"(r[1]) : "r"(addr));
}
__device__ __forceinline__ void bf16_split2(float x, float y, uint32_t& hi, uint32_t& lo) {
    __nv_bfloat16 hx = __float2bfloat16(x);
    __nv_bfloat16 hy = __float2bfloat16(y);
    __nv_bfloat16 lx = __float2bfloat16(x - __bfloat162float(hx));
    __nv_bfloat16 ly = __float2bfloat16(y - __bfloat162float(hy));
    hi = (uint32_t)__bfloat16_as_ushort(hx) | ((uint32_t)__bfloat16_as_ushort(hy) << 16);
    lo = (uint32_t)__bfloat16_as_ushort(lx) | ((uint32_t)__bfloat16_as_ushort(ly) << 16);
}
__device__ __forceinline__ uint32_t fp16_pack2(float x, float y) {
    __half2 h = __floats2half2_rn(x, y);
    return *(uint32_t*)&h;
}

// ---------------------------------------------------------------------------
// GEMM core: C[M,N] = A[M,K] @ B[K,N], CTA 128x128, BK=32, 8 warps 2x4.
// DOUBLE-BUFFERED smem, ONE __syncthreads per K-block:
//   prefetch LDG(k+1) -> compute MMA from buf[cur] -> cvt+STS(k+1)->buf[1-cur]
//   (disjoint buffers: no fence between compute and store) -> barrier.
// PASSES=3: bf16 hi/lo 3-term split. PASSES=1: 1-pass fp16.
// X4T=1 only legal in bf3-free kernels (regalloc — R12 lesson).
// ---------------------------------------------------------------------------
template<int PASSES, int X4T>
__device__ __forceinline__ void gemm_core(
    const float* __restrict__ A, const float* __restrict__ Bm, float* __restrict__ C,
    int N, int K, int row0, int col0, char* smraw)
{
    const uint32_t sb = (uint32_t)__cvta_generic_to_shared(smraw);
    constexpr int AHo = 0;
    constexpr int ALo = 10240;
    constexpr int BHo = (PASSES == 3) ? 20480 : 10240;
    constexpr int BLo = 29184;
    constexpr int BUFSZ = (PASSES == 3) ? 37888 : 18944;

    const int tid  = threadIdx.x;
    const int lane = tid & 31;
    const int warp = tid >> 5;
    const int grp  = lane >> 2;
    const int qid  = lane & 3;
    const int wm   = (warp >> 2) * 64;
    const int wn   = (warp & 3) * 32;

    float acc[4][4][4];
    #pragma unroll
    for (int i = 0; i < 4; i++)
        #pragma unroll
        for (int j = 0; j < 4; j++)
            #pragma unroll
            for (int c = 0; c < 4; c++) acc[i][j][c] = 0.f;

    float4 aReg[4], bReg[4];
    // prefetch tile 0
    #pragma unroll
    for (int i = 0; i < 4; i++) {
        int idx = tid + i * 256;
        int ar = idx >> 3, ac = (idx & 7) << 2;
        aReg[i] = *(const float4*)(A + (size_t)(row0 + ar) * K + ac);
        int bk = idx >> 5, bn = (idx & 31) << 2;
        bReg[i] = *(const float4*)(Bm + (size_t)bk * N + col0 + bn);
    }
    // store tile 0 into buffer 0
    #pragma unroll
    for (int i = 0; i < 4; i++) {
        int idx = tid + i * 256;
        int ar = idx >> 3, ac = (idx & 7) << 2;
        int aoff = (ar * 40 + ac) << 1;
        int bk = idx >> 5, bn = (idx & 31) << 2;
        int boff = (bk * 136 + bn) << 1;
        if (PASSES == 3) {
            uint32_t h01, l01, h23, l23;
            bf16_split2(aReg[i].x, aReg[i].y, h01, l01);
            bf16_split2(aReg[i].z, aReg[i].w, h23, l23);
            *(uint2*)(smraw + AHo + aoff) = make_uint2(h01, h23);
            *(uint2*)(smraw + ALo + aoff) = make_uint2(l01, l23);
            bf16_split2(bReg[i].x, bReg[i].y, h01, l01);
            bf16_split2(bReg[i].z, bReg[i].w, h23, l23);
            *(uint2*)(smraw + BHo + boff) = make_uint2(h01, h23);
            *(uint2*)(smraw + BLo + boff) = make_uint2(l01, l23);
        } else {
            *(uint2*)(smraw + AHo + aoff) =
                make_uint2(fp16_pack2(aReg[i].x, aReg[i].y), fp16_pack2(aReg[i].z, aReg[i].w));
            *(uint2*)(smraw + BHo + boff) =
                make_uint2(fp16_pack2(bReg[i].x, bReg[i].y), fp16_pack2(bReg[i].z, bReg[i].w));
        }
    }
    __syncthreads();

    const int nkb = K >> 5;
    for (int kb = 0; kb < nkb; kb++) {
        const int curo = (kb & 1) * BUFSZ;
        const int nxto = BUFSZ - curo;
        const bool more = (kb + 1 < nkb);

        // prefetch next tile (LDG latency covered by the MMA loop below)
        if (more) {
            const int k0n = (kb + 1) << 5;
            #pragma unroll
            for (int i = 0; i < 4; i++) {
                int idx = tid + i * 256;
                int ar = idx >> 3, ac = (idx & 7) << 2;
                aReg[i] = *(const float4*)(A + (size_t)(row0 + ar) * K + k0n + ac);
                int bk = idx >> 5, bn = (idx & 31) << 2;
                bReg[i] = *(const float4*)(Bm + (size_t)(k0n + bk) * N + col0 + bn);
            }
        }

        // compute from current buffer
        #pragma unroll
        for (int kk = 0; kk < 32; kk += 16) {
            uint32_t ah[4][4], al[4][4];
            #pragma unroll
            for (int im = 0; im < 4; im++) {
                int m = wm + im * 16 + (lane & 15);
                uint32_t ab = sb + curo + AHo + ((m * 40 + kk + ((lane >> 4) << 3)) << 1);
                ldsm_x4(ah[im], ab);
                if (PASSES == 3) ldsm_x4(al[im], ab + (ALo - AHo));
            }
            uint32_t bh[4][2], bl[4][2];
            if (X4T) {
                #pragma unroll
                for (int pr = 0; pr < 2; pr++) {
                    int kr = kk + (lane & 15);
                    uint32_t bb = sb + curo + BHo + ((kr * 136 + wn + pr * 16 + ((lane >> 4) << 3)) << 1);
                    uint32_t t4[4];
                    ldsm_x4t(t4, bb);
                    bh[2*pr][0] = t4[0]; bh[2*pr][1] = t4[1];
                    bh[2*pr+1][0] = t4[2]; bh[2*pr+1][1] = t4[3];
                    if (PASSES == 3) {
                        ldsm_x4t(t4, bb + (BLo - BHo));
                        bl[2*pr][0] = t4[0]; bl[2*pr][1] = t4[1];
                        bl[2*pr+1][0] = t4[2]; bl[2*pr+1][1] = t4[3];
                    }
                }
            } else {
                #pragma unroll
                for (int in_ = 0; in_ < 4; in_++) {
                    int kr = kk + (lane & 15);
                    uint32_t bb = sb + curo + BHo + ((kr * 136 + wn + in_ * 8) << 1);
                    ldsm_x2t(bh[in_], bb);
                    if (PASSES == 3) ldsm_x2t(bl[in_], bb + (BLo - BHo));
                }
            }
            #pragma unroll
            for (int im = 0; im < 4; im++)
                #pragma unroll
                for (int in_ = 0; in_ < 4; in_++) {
                    if (PASSES == 3) {
                        mma_bf16(acc[im][in_], ah[im], bh[in_]);
                        mma_bf16(acc[im][in_], ah[im], bl[in_]);
                        mma_bf16(acc[im][in_], al[im], bh[in_]);
                    } else {
                        mma_fp16(acc[im][in_], ah[im], bh[in_]);
                    }
                }
        }

        // store next tile into the other buffer (disjoint from reads above)
        if (more) {
            #pragma unroll
            for (int i = 0; i < 4; i++) {
                int idx = tid + i * 256;
                int ar = idx >> 3, ac = (idx & 7) << 2;
                int aoff = (ar * 40 + ac) << 1;
                int bk = idx >> 5, bn = (idx & 31) << 2;
                int boff = (bk * 136 + bn) << 1;
                if (PASSES == 3) {
                    uint32_t h01, l01, h23, l23;
                    bf16_split2(aReg[i].x, aReg[i].y, h01, l01);
                    bf16_split2(aReg[i].z, aReg[i].w, h23, l23);
                    *(uint2*)(smraw + nxto + AHo + aoff) = make_uint2(h01, h23);
                    *(uint2*)(smraw + nxto + ALo + aoff) = make_uint2(l01, l23);
                    bf16_split2(bReg[i].x, bReg[i].y, h01, l01);
                    bf16_split2(bReg[i].z, bReg[i].w, h23, l23);
                    *(uint2*)(smraw + nxto + BHo + boff) = make_uint2(h01, h23);
                    *(uint2*)(smraw + nxto + BLo + boff) = make_uint2(l01, l23);
                } else {
                    *(uint2*)(smraw + nxto + AHo + aoff) =
                        make_uint2(fp16_pack2(aReg[i].x, aReg[i].y), fp16_pack2(aReg[i].z, aReg[i].w));
                    *(uint2*)(smraw + nxto + BHo + boff) =
                        make_uint2(fp16_pack2(bReg[i].x, bReg[i].y), fp16_pack2(bReg[i].z, bReg[i].w));
                }
            }
            __syncthreads();
        }
    }

    #pragma unroll
    for (int im = 0; im < 4; im++) {
        int r = row0 + wm + im * 16 + grp;
        #pragma unroll
        for (int in_ = 0; in_ < 4; in_++) {
            int nc = col0 + wn + in_ * 8 + 2 * qid;
            *(float2*)(C + (size_t)r * N + nc)       = make_float2(acc[im][in_][0], acc[im][in_][1]);
            *(float2*)(C + (size_t)(r + 8) * N + nc) = make_float2(acc[im][in_][2], acc[im][in_][3]);
        }
    }
}

// Merged Q/K/V projections, occ-2, all-x2t (R12 rule).
__global__ void __launch_bounds__(256, 2) proj_qkv(
    const float* __restrict__ Xq, const float* __restrict__ Wq, float* __restrict__ Cq,
    const float* __restrict__ Xkv, const float* __restrict__ Wk, float* __restrict__ Ck,
    const float* __restrict__ Wv, float* __restrict__ Cv)
{
    extern __shared__ char smraw[];
    const int bx = blockIdx.x;
    const int row0 = blockIdx.y * 128;
    if (bx < 16)
        gemm_core<3, 0>(Xq, Wq, Cq, 2048, 2048, row0, bx * 128, smraw);
    else if (bx < 20)
        gemm_core<3, 0>(Xkv, Wk, Ck, 512, 2048, row0, (bx - 16) * 128, smraw);
    else
        gemm_core<1, 0>(Xkv, Wv, Cv, 512, 2048, row0, (bx - 20) * 128, smraw);
}

// Output projection (fp16 1-pass, x4t — standalone kernel), occ-2.
__global__ void __launch_bounds__(256, 2) gemm_o(
    const float* __restrict__ A, const float* __restrict__ Bm, float* __restrict__ C)
{
    extern __shared__ char smraw[];
    gemm_core<1, 1>(A, Bm, C, 2048, 2048, blockIdx.y * 128, blockIdx.x * 128, smraw);
}

// ---------------- RoPE fused (q then k ranges in one grid) ----------------
#define QROPE_TOTAL (B_*T_*NQ*64)
#define KROPE_TOTAL (B_*S_*NKV*64)

__global__ void rope_fused(float* __restrict__ xq, float* __restrict__ xk,
                           const int* __restrict__ qpos, const int* __restrict__ kpos)
{
    int idx = blockIdx.x * blockDim.x + threadIdx.x;
    float* x;
    const int* pos;
    int Nh;
    if (idx < QROPE_TOTAL) {
        x = xq; pos = qpos; Nh = NQ;
    } else {
        idx -= QROPE_TOTAL;
        if (idx >= KROPE_TOTAL) return;
        x = xk; pos = kpos; Nh = NKV;
    }
    int i   = idx & 63;
    int bln = idx >> 6;
    int bl  = bln / Nh;
    float p    = (float)pos[bl];
    float frac = (float)i * (1.0f / 64.0f);
    float ts   = powf(10000.0f, frac);
    float ang  = p / ts;
    float si = sinf(ang), co = cosf(ang);
    float* base = x + (size_t)bln * HD;
    float x1 = base[i], x2 = base[i + 64];
    base[i]      = x1 * co - x2 * si;
    base[i + 64] = x2 * co + x1 * si;
}

// ---------------------------------------------------------------------------
// Flash attention (R9-verified, byte-identical): occ-2, KV block 32,
// bf16-3x QK^T, fp16 PV with register-built A fragments.
// Smem: QH 0 (34816), QL 34816, KH 69632 (8704), KL 78336, VS 87040 (8704).
// Total 95744 -> 2 CTAs/SM.
// ---------------------------------------------------------------------------
#define A_QH 0
#define A_QL 34816
#define A_KH 69632
#define A_KL 78336
#define A_VS 87040
#define A_SMEM 95744
#define VSH 136

__global__ void __launch_bounds__(256, 2) attn_tc_kernel(
    const float* __restrict__ q, const float* __restrict__ k,
    const float* __restrict__ v, float* __restrict__ o)
{
    extern __shared__ char smraw[];
    const uint32_t sb = (uint32_t)__cvta_generic_to_shared(smraw);

    const int tid  = threadIdx.x;
    const int lane = tid & 31;
    const int warp = tid >> 5;
    const int grp  = lane >> 2;
    const int qid  = lane & 3;
    const int wm   = warp * 16;
    const int t0   = blockIdx.x * 128;
    const int n    = blockIdx.y;
    const int b    = blockIdx.z;
    const int kvh  = n >> 2;

    const float* Qg = q + ((size_t)(b * T_ + t0) * NQ  + n)   * HD;
    const float* Kg = k + ((size_t)(b * S_)      * NKV + kvh) * HD;
    const float* Vg = v + ((size_t)(b * S_)      * NKV + kvh) * HD;

    for (int f = tid; f < 128 * 32; f += 256) {
        int r = f >> 5, c4 = (f & 31) << 2;
        float4 a = *(const float4*)(Qg + (size_t)r * (NQ * HD) + c4);
        uint32_t h01, l01, h23, l23;
        bf16_split2(a.x, a.y, h01, l01);
        bf16_split2(a.z, a.w, h23, l23);
        int off = (r * 136 + c4) << 1;
        *(uint2*)(smraw + A_QH + off) = make_uint2(h01, h23);
        *(uint2*)(smraw + A_QL + off) = make_uint2(l01, l23);
    }

    float m0 = -1e30f, m1 = -1e30f, l0 = 0.f, l1 = 0.f;
    float oacc[16][4];
    #pragma unroll
    for (int j = 0; j < 16; j++)
        #pragma unroll
        for (int c = 0; c < 4; c++) oacc[j][c] = 0.f;

    for (int blk = 0; blk < 32; blk++) {
        __syncthreads();
        {
            const int s0 = blk * 32;
            #pragma unroll
            for (int i = 0; i < 4; i++) {
                int f = tid + i * 256;
                int r = f >> 5, c4 = (f & 31) << 2;
                float4 a = *(const float4*)(Kg + (size_t)(s0 + r) * (NKV * HD) + c4);
                uint32_t h01, l01, h23, l23;
                bf16_split2(a.x, a.y, h01, l01);
                bf16_split2(a.z, a.w, h23, l23);
                int off = (r * 136 + c4) << 1;
                *(uint2*)(smraw + A_KH + off) = make_uint2(h01, h23);
                *(uint2*)(smraw + A_KL + off) = make_uint2(l01, l23);
                float4 vv = *(const float4*)(Vg + (size_t)(s0 + r) * (NKV * HD) + c4);
                *(uint2*)(smraw + A_VS + ((r * VSH + c4) << 1)) =
                    make_uint2(fp16_pack2(vv.x, vv.y), fp16_pack2(vv.z, vv.w));
            }
        }
        __syncthreads();

        float sacc[4][4];
        #pragma unroll
        for (int j = 0; j < 4; j++)
            #pragma unroll
            for (int c = 0; c < 4; c++) sacc[j][c] = 0.f;

        #pragma unroll
        for (int kk = 0; kk < 8; kk++) {
            const int col0h = kk * 16;
            uint32_t ah[4], al[4];
            {
                int m = wm + (lane & 15);
                uint32_t ab = sb + A_QH + ((m * 136 + col0h + ((lane >> 4) << 3)) << 1);
                ldsm_x4(ah, ab);
                ldsm_x4(al, ab + (A_QL - A_QH));
            }
            #pragma unroll
            for (int j2 = 0; j2 < 2; j2++) {
                int row = (j2 * 2 + (lane >> 4)) * 8 + (lane & 7);
                uint32_t bb = sb + A_KH + ((row * 136 + col0h + (lane & 8)) << 1);
                uint32_t bh4[4], bl4[4];
                ldsm_x4(bh4, bb);
                ldsm_x4(bl4, bb + (A_KL - A_KH));
                mma_bf16(sacc[2*j2],   ah, bh4);
                mma_bf16(sacc[2*j2],   ah, bl4);
                mma_bf16(sacc[2*j2],   al, bh4);
                mma_bf16(sacc[2*j2+1], ah, bh4 + 2);
                mma_bf16(sacc[2*j2+1], ah, bl4 + 2);
                mma_bf16(sacc[2*j2+1], al, bh4 + 2);
            }
        }

        float mx0 = -1e30f, mx1 = -1e30f;
        #pragma unroll
        for (int j = 0; j < 4; j++) {
            mx0 = fmaxf(mx0, fmaxf(sacc[j][0], sacc[j][1]));
            mx1 = fmaxf(mx1, fmaxf(sacc[j][2], sacc[j][3]));
        }
        #pragma unroll
        for (int off = 1; off < 4; off <<= 1) {
            mx0 = fmaxf(mx0, __shfl_xor_sync(0xffffffffu, mx0, off));
            mx1 = fmaxf(mx1, __shfl_xor_sync(0xffffffffu, mx1, off));
        }
        float mn0 = fmaxf(m0, mx0), mn1 = fmaxf(m1, mx1);
        float cr0 = __expf(m0 - mn0), cr1 = __expf(m1 - mn1);
        float ps0 = 0.f, ps1 = 0.f;
        uint32_t pk[4][2];
        #pragma unroll
        for (int j = 0; j < 4; j++) {
            float e0 = __expf(sacc[j][0] - mn0);
            float e1 = __expf(sacc[j][1] - mn0);
            float e2 = __expf(sacc[j][2] - mn1);
            float e3 = __expf(sacc[j][3] - mn1);
            ps0 += e0 + e1; ps1 += e2 + e3;
            pk[j][0] = fp16_pack2(e0, e1);
            pk[j][1] = fp16_pack2(e2, e3);
        }
        #pragma unroll
        for (int off = 1; off < 4; off <<= 1) {
            ps0 += __shfl_xor_sync(0xffffffffu, ps0, off);
            ps1 += __shfl_xor_sync(0xffffffffu, ps1, off);
        }
        l0 = l0 * cr0 + ps0; m0 = mn0;
        l1 = l1 * cr1 + ps1; m1 = mn1;
        #pragma unroll
        for (int j = 0; j < 16; j++) {
            oacc[j][0] *= cr0; oacc[j][1] *= cr0;
            oacc[j][2] *= cr1; oacc[j][3] *= cr1;
        }

        #pragma unroll
        for (int kk2 = 0; kk2 < 2; kk2++) {
            uint32_t pa[4] = { pk[2*kk2][0], pk[2*kk2][1], pk[2*kk2+1][0], pk[2*kk2+1][1] };
            #pragma unroll
            for (int j2 = 0; j2 < 8; j2++) {
                int kr  = kk2 * 16 + (lane & 15);
                int col = (j2 * 2 + (lane >> 4)) * 8;
                uint32_t vb4[4];
                ldsm_x4t(vb4, sb + A_VS + ((kr * VSH + col) << 1));
                mma_fp16(oacc[2*j2],     pa, vb4);
                mma_fp16(oacc[2*j2 + 1], pa, vb4 + 2);
            }
        }
    }

    float inv0 = 1.0f / l0, inv1 = 1.0f / l1;
    float* o0 = o + ((size_t)(b * T_ + t0 + wm + grp)     * NQ + n) * HD;
    float* o1 = o + ((size_t)(b * T_ + t0 + wm + grp + 8) * NQ + n) * HD;
    #pragma unroll
    for (int j = 0; j < 16; j++) {
        int col = j * 8 + 2 * qid;
        *(float2*)(o0 + col) = make_float2(oacc[j][0] * inv0, oacc[j][1] * inv0);
        *(float2*)(o1 + col) = make_float2(oacc[j][2] * inv1, oacc[j][3] * inv1);
    }
}

// ---------------- Launch ----------------
extern "C" void kernel_launch(void* const* d_in, const int* in_sizes, int n_in,
                              void* d_out, int out_size)
{
    const float* Xq  = (const float*)d_in[0];
    const float* Xkv = (const float*)d_in[1];
    const int*   qpos = (const int*)d_in[2];
    const int*   kpos = (const int*)d_in[3];
    const float* Wq  = (const float*)d_in[4];
    const float* Wk  = (const float*)d_in[5];
    const float* Wv  = (const float*)d_in[6];
    const float* Wo  = (const float*)d_in[7];
    float* out = (float*)d_out;

    float *qb, *kb, *vb, *ab;
    cudaGetSymbolAddress((void**)&qb, g_q);
    cudaGetSymbolAddress((void**)&kb, g_k);
    cudaGetSymbolAddress((void**)&vb, g_v);
    cudaGetSymbolAddress((void**)&ab, g_attn);

    const int P_SMEM = 2 * 37888;   // 75776 (double-buffered bf3 layout)
    const int O_SMEM = 2 * 18944;   // 37888 (double-buffered fp16 layout)
    cudaFuncSetAttribute(proj_qkv, cudaFuncAttributeMaxDynamicSharedMemorySize, P_SMEM);
    cudaFuncSetAttribute(gemm_o, cudaFuncAttributeMaxDynamicSharedMemorySize, O_SMEM);
    cudaFuncSetAttribute(attn_tc_kernel, cudaFuncAttributeMaxDynamicSharedMemorySize, A_SMEM);

    // Q/K/V projections in one launch (occ-2, double-buffered, 1 barrier/K-block)
    proj_qkv<<<dim3(24, 16), 256, P_SMEM>>>(Xq, Wq, qb, Xkv, Wk, kb, Wv, vb);

    // RoPE on q and k, one launch
    rope_fused<<<(QROPE_TOTAL + KROPE_TOTAL + 255) / 256, 256>>>(qb, kb, qpos, kpos);

    // Attention (R9 config, byte-identical)
    attn_tc_kernel<<<dim3(T_/128, NQ, B_), 256, A_SMEM>>>(qb, kb, vb, ab);

    // Output projection (occ-2, x4t, double-buffered)
    gemm_o<<<dim3(16, 16), 256, O_SMEM>>>(ab, Wo, out);
}

// round 15
// speedup vs baseline: 1.0942x; 1.0942x over previous
#include <cuda_runtime.h>
#include <cuda_bf16.h>
#include <cuda_fp16.h>
#include <cstdint>

#define B_  2
#define T_  1024
#define S_  1024
#define NQ  16
#define NKV 4
#define HD  128

// Scratch (allocation-free rule: __device__ globals)
__device__ float g_q[B_*T_*NQ*HD];      // (B,T,NQ,HD)
__device__ float g_k[B_*S_*NKV*HD];     // (B,S,NKV,HD)
__device__ float g_v[B_*S_*NKV*HD];
__device__ __align__(256) uint16_t g_attn_h[B_*T_*NQ*HD];   // attention out, fp16

// ---------------------------------------------------------------------------
// helpers
// ---------------------------------------------------------------------------
__device__ __forceinline__ void mma_bf16(float d[4], const uint32_t a[4], const uint32_t b[2]) {
    asm volatile(
        "mma.sync.aligned.m16n8k16.row.col.f32.bf16.bf16.f32 "
        "{%0,%1,%2,%3}, {%4,%5,%6,%7}, {%8,%9}, {%0,%1,%2,%3};\n"
        : "+f"(d[0]), "+f"(d[1]), "+f"(d[2]), "+f"(d[3])
        : "r"(a[0]), "r"(a[1]), "r"(a[2]), "r"(a[3]), "r"(b[0]), "r"(b[1]));
}
__device__ __forceinline__ void mma_fp16(float d[4], const uint32_t a[4], const uint32_t b[2]) {
    asm volatile(
        "mma.sync.aligned.m16n8k16.row.col.f32.f16.f16.f32 "
        "{%0,%1,%2,%3}, {%4,%5,%6,%7}, {%8,%9}, {%0,%1,%2,%3};\n"
        : "+f"(d[0]), "+f"(d[1]), "+f"(d[2]), "+f"(d[3])
        : "r"(a[0]), "r"(a[1]), "r"(a[2]), "r"(a[3]), "r"(b[0]), "r"(b[1]));
}
__device__ __forceinline__ void ldsm_x4(uint32_t r[4], uint32_t addr) {
    asm volatile("ldmatrix.sync.aligned.m8n8.x4.shared.b16 {%0,%1,%2,%3}, [%4];"
                 : "=r"(r[0]), "=r"(r[1]), "=r"(r[2]), "=r"(r[3]) : "r"(addr));
}
__device__ __forceinline__ void ldsm_x4t(uint32_t r[4], uint32_t addr) {
    asm volatile("ldmatrix.sync.aligned.m8n8.x4.trans.shared.b16 {%0,%1,%2,%3}, [%4];"
                 : "=r"(r[0]), "=r"(r[1]), "=r"(r[2]), "=r"(r[3]) : "r"(addr));
}
__device__ __forceinline__ void ldsm_x2t(uint32_t r[2], uint32_t addr) {
    asm volatile("ldmatrix.sync.aligned.m8n8.x2.trans.shared.b16 {%0,%1}, [%2];"
                 : "=r"(r[0]), "=r"(r[1]) : "r"(addr));
}
__device__ __forceinline__ void bf16_split2(float x, float y, uint32_t& hi, uint32_t& lo) {
    __nv_bfloat16 hx = __float2bfloat16(x);
    __nv_bfloat16 hy = __float2bfloat16(y);
    __nv_bfloat16 lx = __float2bfloat16(x - __bfloat162float(hx));
    __nv_bfloat16 ly = __float2bfloat16(y - __bfloat162float(hy));
    hi = (uint32_t)__bfloat16_as_ushort(hx) | ((uint32_t)__bfloat16_as_ushort(hy) << 16);
    lo = (uint32_t)__bfloat16_as_ushort(lx) | ((uint32_t)__bfloat16_as_ushort(ly) << 16);
}
__device__ __forceinline__ uint32_t fp16_pack2(float x, float y) {
    __half2 h = __floats2half2_rn(x, y);
    return *(uint32_t*)&h;
}

// ---------------------------------------------------------------------------
// GEMM core (R13-exact, single-buffer): C[M,N] = A[M,K] @ B[K,N], CTA 128x128,
// BK=32, 8 warps 2x4. PASSES=3: bf16 3-term split. PASSES=1: fp16.
// X4T=1 only in bf3-free kernels (regalloc rule, R11/R12/R14 evidence).
// ---------------------------------------------------------------------------
template<int PASSES, int X4T>
__device__ __forceinline__ void gemm_core(
    const float* __restrict__ A, const float* __restrict__ Bm, float* __restrict__ C,
    int N, int K, int row0, int col0, char* smraw)
{
    const uint32_t sb = (uint32_t)__cvta_generic_to_shared(smraw);
    constexpr int AHo = 0;
    constexpr int ALo = 10240;
    constexpr int BHo = (PASSES == 3) ? 20480 : 10240;
    constexpr int BLo = 29184;

    const int tid  = threadIdx.x;
    const int lane = tid & 31;
    const int warp = tid >> 5;
    const int grp  = lane >> 2;
    const int qid  = lane & 3;
    const int wm   = (warp >> 2) * 64;
    const int wn   = (warp & 3) * 32;

    float acc[4][4][4];
    #pragma unroll
    for (int i = 0; i < 4; i++)
        #pragma unroll
        for (int j = 0; j < 4; j++)
            #pragma unroll
            for (int c = 0; c < 4; c++) acc[i][j][c] = 0.f;

    float4 aReg[4], bReg[4];
    #pragma unroll
    for (int i = 0; i < 4; i++) {
        int idx = tid + i * 256;
        int ar = idx >> 3, ac = (idx & 7) << 2;
        aReg[i] = *(const float4*)(A + (size_t)(row0 + ar) * K + ac);
        int bk = idx >> 5, bn = (idx & 31) << 2;
        bReg[i] = *(const float4*)(Bm + (size_t)bk * N + col0 + bn);
    }

    for (int k0 = 0; k0 < K; k0 += 32) {
        #pragma unroll
        for (int i = 0; i < 4; i++) {
            int idx = tid + i * 256;
            int ar = idx >> 3, ac = (idx & 7) << 2;
            int aoff = (ar * 40 + ac) << 1;
            int bk = idx >> 5, bn = (idx & 31) << 2;
            int boff = (bk * 136 + bn) << 1;
            if (PASSES == 3) {
                uint32_t h01, l01, h23, l23;
                bf16_split2(aReg[i].x, aReg[i].y, h01, l01);
                bf16_split2(aReg[i].z, aReg[i].w, h23, l23);
                *(uint2*)(smraw + AHo + aoff) = make_uint2(h01, h23);
                *(uint2*)(smraw + ALo + aoff) = make_uint2(l01, l23);
                bf16_split2(bReg[i].x, bReg[i].y, h01, l01);
                bf16_split2(bReg[i].z, bReg[i].w, h23, l23);
                *(uint2*)(smraw + BHo + boff) = make_uint2(h01, h23);
                *(uint2*)(smraw + BLo + boff) = make_uint2(l01, l23);
            } else {
                *(uint2*)(smraw + AHo + aoff) =
                    make_uint2(fp16_pack2(aReg[i].x, aReg[i].y), fp16_pack2(aReg[i].z, aReg[i].w));
                *(uint2*)(smraw + BHo + boff) =
                    make_uint2(fp16_pack2(bReg[i].x, bReg[i].y), fp16_pack2(bReg[i].z, bReg[i].w));
            }
        }
        __syncthreads();

        if (k0 + 32 < K) {
            #pragma unroll
            for (int i = 0; i < 4; i++) {
                int idx = tid + i * 256;
                int ar = idx >> 3, ac = (idx & 7) << 2;
                aReg[i] = *(const float4*)(A + (size_t)(row0 + ar) * K + k0 + 32 + ac);
                int bk = idx >> 5, bn = (idx & 31) << 2;
                bReg[i] = *(const float4*)(Bm + (size_t)(k0 + 32 + bk) * N + col0 + bn);
            }
        }

        #pragma unroll
        for (int kk = 0; kk < 32; kk += 16) {
            uint32_t ah[4][4], al[4][4];
            #pragma unroll
            for (int im = 0; im < 4; im++) {
                int m = wm + im * 16 + (lane & 15);
                uint32_t ab = sb + AHo + ((m * 40 + kk + ((lane >> 4) << 3)) << 1);
                ldsm_x4(ah[im], ab);
                if (PASSES == 3) ldsm_x4(al[im], ab + (ALo - AHo));
            }
            uint32_t bh[4][2], bl[4][2];
            if (X4T) {
                #pragma unroll
                for (int pr = 0; pr < 2; pr++) {
                    int kr = kk + (lane & 15);
                    uint32_t bb = sb + BHo + ((kr * 136 + wn + pr * 16 + ((lane >> 4) << 3)) << 1);
                    uint32_t t4[4];
                    ldsm_x4t(t4, bb);
                    bh[2*pr][0] = t4[0]; bh[2*pr][1] = t4[1];
                    bh[2*pr+1][0] = t4[2]; bh[2*pr+1][1] = t4[3];
                    if (PASSES == 3) {
                        ldsm_x4t(t4, bb + (BLo - BHo));
                        bl[2*pr][0] = t4[0]; bl[2*pr][1] = t4[1];
                        bl[2*pr+1][0] = t4[2]; bl[2*pr+1][1] = t4[3];
                    }
                }
            } else {
                #pragma unroll
                for (int in_ = 0; in_ < 4; in_++) {
                    int kr = kk + (lane & 15);
                    uint32_t bb = sb + BHo + ((kr * 136 + wn + in_ * 8) << 1);
                    ldsm_x2t(bh[in_], bb);
                    if (PASSES == 3) ldsm_x2t(bl[in_], bb + (BLo - BHo));
                }
            }
            #pragma unroll
            for (int im = 0; im < 4; im++)
                #pragma unroll
                for (int in_ = 0; in_ < 4; in_++) {
                    if (PASSES == 3) {
                        mma_bf16(acc[im][in_], ah[im], bh[in_]);
                        mma_bf16(acc[im][in_], ah[im], bl[in_]);
                        mma_bf16(acc[im][in_], al[im], bh[in_]);
                    } else {
                        mma_fp16(acc[im][in_], ah[im], bh[in_]);
                    }
                }
        }
        __syncthreads();
    }

    #pragma unroll
    for (int im = 0; im < 4; im++) {
        int r = row0 + wm + im * 16 + grp;
        #pragma unroll
        for (int in_ = 0; in_ < 4; in_++) {
            int nc = col0 + wn + in_ * 8 + 2 * qid;
            *(float2*)(C + (size_t)r * N + nc)       = make_float2(acc[im][in_][0], acc[im][in_][1]);
            *(float2*)(C + (size_t)(r + 8) * N + nc) = make_float2(acc[im][in_][2], acc[im][in_][3]);
        }
    }
}

// Merged Q/K/V projections, occ-2, all-x2t (R12 rule), single-buffer (R14 rule).
__global__ void __launch_bounds__(256, 2) proj_qkv(
    const float* __restrict__ Xq, const float* __restrict__ Wq, float* __restrict__ Cq,
    const float* __restrict__ Xkv, const float* __restrict__ Wk, float* __restrict__ Ck,
    const float* __restrict__ Wv, float* __restrict__ Cv)
{
    extern __shared__ char smraw[];
    const int bx = blockIdx.x;
    const int row0 = blockIdx.y * 128;
    if (bx < 16)
        gemm_core<3, 0>(Xq, Wq, Cq, 2048, 2048, row0, bx * 128, smraw);
    else if (bx < 20)
        gemm_core<3, 0>(Xkv, Wk, Ck, 512, 2048, row0, (bx - 16) * 128, smraw);
    else
        gemm_core<1, 0>(Xkv, Wv, Cv, 512, 2048, row0, (bx - 20) * 128, smraw);
}

// ---------------------------------------------------------------------------
// Output projection with fp16 A input (attention already emits fp16):
// A-fill = pure LDG.64 -> STS.64, no cvt. B (Wo fp32) converted as before.
// Standalone kernel: x4t legal. occ-2, single-buffer.
// ---------------------------------------------------------------------------
__global__ void __launch_bounds__(256, 2) gemm_o(
    const uint16_t* __restrict__ A, const float* __restrict__ Bm, float* __restrict__ C)
{
    extern __shared__ char smraw[];
    const uint32_t sb = (uint32_t)__cvta_generic_to_shared(smraw);
    constexpr int AHo = 0;
    constexpr int BHo = 10240;
    const int N = 2048, K = 2048;

    const int tid  = threadIdx.x;
    const int lane = tid & 31;
    const int warp = tid >> 5;
    const int grp  = lane >> 2;
    const int qid  = lane & 3;
    const int wm   = (warp >> 2) * 64;
    const int wn   = (warp & 3) * 32;
    const int row0 = blockIdx.y * 128;
    const int col0 = blockIdx.x * 128;

    float acc[4][4][4];
    #pragma unroll
    for (int i = 0; i < 4; i++)
        #pragma unroll
        for (int j = 0; j < 4; j++)
            #pragma unroll
            for (int c = 0; c < 4; c++) acc[i][j][c] = 0.f;

    uint2 aReg[4];
    float4 bReg[4];
    #pragma unroll
    for (int i = 0; i < 4; i++) {
        int idx = tid + i * 256;
        int ar = idx >> 3, ac = (idx & 7) << 2;
        aReg[i] = *(const uint2*)(A + (size_t)(row0 + ar) * K + ac);
        int bk = idx >> 5, bn = (idx & 31) << 2;
        bReg[i] = *(const float4*)(Bm + (size_t)bk * N + col0 + bn);
    }

    for (int k0 = 0; k0 < K; k0 += 32) {
        #pragma unroll
        for (int i = 0; i < 4; i++) {
            int idx = tid + i * 256;
            int ar = idx >> 3, ac = (idx & 7) << 2;
            *(uint2*)(smraw + AHo + ((ar * 40 + ac) << 1)) = aReg[i];
            int bk = idx >> 5, bn = (idx & 31) << 2;
            *(uint2*)(smraw + BHo + ((bk * 136 + bn) << 1)) =
                make_uint2(fp16_pack2(bReg[i].x, bReg[i].y), fp16_pack2(bReg[i].z, bReg[i].w));
        }
        __syncthreads();

        if (k0 + 32 < K) {
            #pragma unroll
            for (int i = 0; i < 4; i++) {
                int idx = tid + i * 256;
                int ar = idx >> 3, ac = (idx & 7) << 2;
                aReg[i] = *(const uint2*)(A + (size_t)(row0 + ar) * K + k0 + 32 + ac);
                int bk = idx >> 5, bn = (idx & 31) << 2;
                bReg[i] = *(const float4*)(Bm + (size_t)(k0 + 32 + bk) * N + col0 + bn);
            }
        }

        #pragma unroll
        for (int kk = 0; kk < 32; kk += 16) {
            uint32_t ah[4][4];
            #pragma unroll
            for (int im = 0; im < 4; im++) {
                int m = wm + im * 16 + (lane & 15);
                ldsm_x4(ah[im], sb + AHo + ((m * 40 + kk + ((lane >> 4) << 3)) << 1));
            }
            uint32_t bh[4][2];
            #pragma unroll
            for (int pr = 0; pr < 2; pr++) {
                int kr = kk + (lane & 15);
                uint32_t t4[4];
                ldsm_x4t(t4, sb + BHo + ((kr * 136 + wn + pr * 16 + ((lane >> 4) << 3)) << 1));
                bh[2*pr][0] = t4[0]; bh[2*pr][1] = t4[1];
                bh[2*pr+1][0] = t4[2]; bh[2*pr+1][1] = t4[3];
            }
            #pragma unroll
            for (int im = 0; im < 4; im++)
                #pragma unroll
                for (int in_ = 0; in_ < 4; in_++)
                    mma_fp16(acc[im][in_], ah[im], bh[in_]);
        }
        __syncthreads();
    }

    #pragma unroll
    for (int im = 0; im < 4; im++) {
        int r = row0 + wm + im * 16 + grp;
        #pragma unroll
        for (int in_ = 0; in_ < 4; in_++) {
            int nc = col0 + wn + in_ * 8 + 2 * qid;
            *(float2*)(C + (size_t)r * N + nc)       = make_float2(acc[im][in_][0], acc[im][in_][1]);
            *(float2*)(C + (size_t)(r + 8) * N + nc) = make_float2(acc[im][in_][2], acc[im][in_][3]);
        }
    }
}

// ---------------- RoPE fused (q then k ranges), powf -> exp2f ----------------
#define QROPE_TOTAL (B_*T_*NQ*64)
#define KROPE_TOTAL (B_*S_*NKV*64)

__global__ void rope_fused(float* __restrict__ xq, float* __restrict__ xk,
                           const int* __restrict__ qpos, const int* __restrict__ kpos)
{
    int idx = blockIdx.x * blockDim.x + threadIdx.x;
    float* x;
    const int* pos;
    int Nh;
    if (idx < QROPE_TOTAL) {
        x = xq; pos = qpos; Nh = NQ;
    } else {
        idx -= QROPE_TOTAL;
        if (idx >= KROPE_TOTAL) return;
        x = xk; pos = kpos; Nh = NKV;
    }
    int i   = idx & 63;
    int bln = idx >> 6;
    int bl  = bln / Nh;
    float p    = (float)pos[bl];
    float frac = (float)i * (1.0f / 64.0f);
    // 1/10000^frac = exp2(-frac*log2(10000))
    float inv_ts = exp2f(frac * -13.287712379549449f);
    float ang  = p * inv_ts;
    float si = sinf(ang), co = cosf(ang);
    float* base = x + (size_t)bln * HD;
    float x1 = base[i], x2 = base[i + 64];
    base[i]      = x1 * co - x2 * si;
    base[i + 64] = x2 * co + x1 * si;
}

// ---------------------------------------------------------------------------
// Flash attention (R9/R13 config; only change: output stored as fp16 pairs).
// Smem: QH 0 (34816), QL 34816, KH 69632 (8704), KL 78336, VS 87040 (8704).
// Total 95744 -> 2 CTAs/SM.
// ---------------------------------------------------------------------------
#define A_QH 0
#define A_QL 34816
#define A_KH 69632
#define A_KL 78336
#define A_VS 87040
#define A_SMEM 95744
#define VSH 136

__global__ void __launch_bounds__(256, 2) attn_tc_kernel(
    const float* __restrict__ q, const float* __restrict__ k,
    const float* __restrict__ v, uint16_t* __restrict__ o)
{
    extern __shared__ char smraw[];
    const uint32_t sb = (uint32_t)__cvta_generic_to_shared(smraw);

    const int tid  = threadIdx.x;
    const int lane = tid & 31;
    const int warp = tid >> 5;
    const int grp  = lane >> 2;
    const int qid  = lane & 3;
    const int wm   = warp * 16;
    const int t0   = blockIdx.x * 128;
    const int n    = blockIdx.y;
    const int b    = blockIdx.z;
    const int kvh  = n >> 2;

    const float* Qg = q + ((size_t)(b * T_ + t0) * NQ  + n)   * HD;
    const float* Kg = k + ((size_t)(b * S_)      * NKV + kvh) * HD;
    const float* Vg = v + ((size_t)(b * S_)      * NKV + kvh) * HD;

    for (int f = tid; f < 128 * 32; f += 256) {
        int r = f >> 5, c4 = (f & 31) << 2;
        float4 a = *(const float4*)(Qg + (size_t)r * (NQ * HD) + c4);
        uint32_t h01, l01, h23, l23;
        bf16_split2(a.x, a.y, h01, l01);
        bf16_split2(a.z, a.w, h23, l23);
        int off = (r * 136 + c4) << 1;
        *(uint2*)(smraw + A_QH + off) = make_uint2(h01, h23);
        *(uint2*)(smraw + A_QL + off) = make_uint2(l01, l23);
    }

    float m0 = -1e30f, m1 = -1e30f, l0 = 0.f, l1 = 0.f;
    float oacc[16][4];
    #pragma unroll
    for (int j = 0; j < 16; j++)
        #pragma unroll
        for (int c = 0; c < 4; c++) oacc[j][c] = 0.f;

    for (int blk = 0; blk < 32; blk++) {
        __syncthreads();
        {
            const int s0 = blk * 32;
            #pragma unroll
            for (int i = 0; i < 4; i++) {
                int f = tid + i * 256;
                int r = f >> 5, c4 = (f & 31) << 2;
                float4 a = *(const float4*)(Kg + (size_t)(s0 + r) * (NKV * HD) + c4);
                uint32_t h01, l01, h23, l23;
                bf16_split2(a.x, a.y, h01, l01);
                bf16_split2(a.z, a.w, h23, l23);
                int off = (r * 136 + c4) << 1;
                *(uint2*)(smraw + A_KH + off) = make_uint2(h01, h23);
                *(uint2*)(smraw + A_KL + off) = make_uint2(l01, l23);
                float4 vv = *(const float4*)(Vg + (size_t)(s0 + r) * (NKV * HD) + c4);
                *(uint2*)(smraw + A_VS + ((r * VSH + c4) << 1)) =
                    make_uint2(fp16_pack2(vv.x, vv.y), fp16_pack2(vv.z, vv.w));
            }
        }
        __syncthreads();

        float sacc[4][4];
        #pragma unroll
        for (int j = 0; j < 4; j++)
            #pragma unroll
            for (int c = 0; c < 4; c++) sacc[j][c] = 0.f;

        #pragma unroll
        for (int kk = 0; kk < 8; kk++) {
            const int col0h = kk * 16;
            uint32_t ah[4], al[4];
            {
                int m = wm + (lane & 15);
                uint32_t ab = sb + A_QH + ((m * 136 + col0h + ((lane >> 4) << 3)) << 1);
                ldsm_x4(ah, ab);
                ldsm_x4(al, ab + (A_QL - A_QH));
            }
            #pragma unroll
            for (int j2 = 0; j2 < 2; j2++) {
                int row = (j2 * 2 + (lane >> 4)) * 8 + (lane & 7);
                uint32_t bb = sb + A_KH + ((row * 136 + col0h + (lane & 8)) << 1);
                uint32_t bh4[4], bl4[4];
                ldsm_x4(bh4, bb);
                ldsm_x4(bl4, bb + (A_KL - A_KH));
                mma_bf16(sacc[2*j2],   ah, bh4);
                mma_bf16(sacc[2*j2],   ah, bl4);
                mma_bf16(sacc[2*j2],   al, bh4);
                mma_bf16(sacc[2*j2+1], ah, bh4 + 2);
                mma_bf16(sacc[2*j2+1], ah, bl4 + 2);
                mma_bf16(sacc[2*j2+1], al, bh4 + 2);
            }
        }

        float mx0 = -1e30f, mx1 = -1e30f;
        #pragma unroll
        for (int j = 0; j < 4; j++) {
            mx0 = fmaxf(mx0, fmaxf(sacc[j][0], sacc[j][1]));
            mx1 = fmaxf(mx1, fmaxf(sacc[j][2], sacc[j][3]));
        }
        #pragma unroll
        for (int off = 1; off < 4; off <<= 1) {
            mx0 = fmaxf(mx0, __shfl_xor_sync(0xffffffffu, mx0, off));
            mx1 = fmaxf(mx1, __shfl_xor_sync(0xffffffffu, mx1, off));
        }
        float mn0 = fmaxf(m0, mx0), mn1 = fmaxf(m1, mx1);
        float cr0 = __expf(m0 - mn0), cr1 = __expf(m1 - mn1);
        float ps0 = 0.f, ps1 = 0.f;
        uint32_t pk[4][2];
        #pragma unroll
        for (int j = 0; j < 4; j++) {
            float e0 = __expf(sacc[j][0] - mn0);
            float e1 = __expf(sacc[j][1] - mn0);
            float e2 = __expf(sacc[j][2] - mn1);
            float e3 = __expf(sacc[j][3] - mn1);
            ps0 += e0 + e1; ps1 += e2 + e3;
            pk[j][0] = fp16_pack2(e0, e1);
            pk[j][1] = fp16_pack2(e2, e3);
        }
        #pragma unroll
        for (int off = 1; off < 4; off <<= 1) {
            ps0 += __shfl_xor_sync(0xffffffffu, ps0, off);
            ps1 += __shfl_xor_sync(0xffffffffu, ps1, off);
        }
        l0 = l0 * cr0 + ps0; m0 = mn0;
        l1 = l1 * cr1 + ps1; m1 = mn1;
        #pragma unroll
        for (int j = 0; j < 16; j++) {
            oacc[j][0] *= cr0; oacc[j][1] *= cr0;
            oacc[j][2] *= cr1; oacc[j][3] *= cr1;
        }

        #pragma unroll
        for (int kk2 = 0; kk2 < 2; kk2++) {
            uint32_t pa[4] = { pk[2*kk2][0], pk[2*kk2][1], pk[2*kk2+1][0], pk[2*kk2+1][1] };
            #pragma unroll
            for (int j2 = 0; j2 < 8; j2++) {
                int kr  = kk2 * 16 + (lane & 15);
                int col = (j2 * 2 + (lane >> 4)) * 8;
                uint32_t vb4[4];
                ldsm_x4t(vb4, sb + A_VS + ((kr * VSH + col) << 1));
                mma_fp16(oacc[2*j2],     pa, vb4);
                mma_fp16(oacc[2*j2 + 1], pa, vb4 + 2);
            }
        }
    }

    // ---- epilogue: write fp16 pairs (same rounding gemm_o would apply) ----
    float inv0 = 1.0f / l0, inv1 = 1.0f / l1;
    uint16_t* o0 = o + ((size_t)(b * T_ + t0 + wm + grp)     * NQ + n) * HD;
    uint16_t* o1 = o + ((size_t)(b * T_ + t0 + wm + grp + 8) * NQ + n) * HD;
    #pragma unroll
    for (int j = 0; j < 16; j++) {
        int col = j * 8 + 2 * qid;
        *(uint32_t*)(o0 + col) = fp16_pack2(oacc[j][0] * inv0, oacc[j][1] * inv0);
        *(uint32_t*)(o1 + col) = fp16_pack2(oacc[j][2] * inv1, oacc[j][3] * inv1);
    }
}

// ---------------- Launch ----------------
extern "C" void kernel_launch(void* const* d_in, const int* in_sizes, int n_in,
                              void* d_out, int out_size)
{
    const float* Xq  = (const float*)d_in[0];
    const float* Xkv = (const float*)d_in[1];
    const int*   qpos = (const int*)d_in[2];
    const int*   kpos = (const int*)d_in[3];
    const float* Wq  = (const float*)d_in[4];
    const float* Wk  = (const float*)d_in[5];
    const float* Wv  = (const float*)d_in[6];
    const float* Wo  = (const float*)d_in[7];
    float* out = (float*)d_out;

    float *qb, *kb, *vb;
    uint16_t* ah;
    cudaGetSymbolAddress((void**)&qb, g_q);
    cudaGetSymbolAddress((void**)&kb, g_k);
    cudaGetSymbolAddress((void**)&vb, g_v);
    cudaGetSymbolAddress((void**)&ah, g_attn_h);

    const int P_SMEM = 37888;
    const int O_SMEM = 18944;
    cudaFuncSetAttribute(proj_qkv, cudaFuncAttributeMaxDynamicSharedMemorySize, P_SMEM);
    cudaFuncSetAttribute(gemm_o, cudaFuncAttributeMaxDynamicSharedMemorySize, O_SMEM);
    cudaFuncSetAttribute(attn_tc_kernel, cudaFuncAttributeMaxDynamicSharedMemorySize, A_SMEM);

    // Q/K/V projections in one launch (R13-exact)
    proj_qkv<<<dim3(24, 16), 256, P_SMEM>>>(Xq, Wq, qb, Xkv, Wk, kb, Wv, vb);

    // RoPE on q and k, one launch (exp2f)
    rope_fused<<<(QROPE_TOTAL + KROPE_TOTAL + 255) / 256, 256>>>(qb, kb, qpos, kpos);

    // Attention (R13 config; fp16 output)
    attn_tc_kernel<<<dim3(T_/128, NQ, B_), 256, A_SMEM>>>(qb, kb, vb, ah);

    // Output projection (fp16 A input, occ-2, x4t)
    gemm_o<<<dim3(16, 16), 256, O_SMEM>>>(ah, Wo, out);
}

// round 16
// speedup vs baseline: 1.1083x; 1.0129x over previous
#include <cuda_runtime.h>
#include <cuda_bf16.h>
#include <cuda_fp16.h>
#include <cstdint>

#define B_  2
#define T_  1024
#define S_  1024
#define NQ  16
#define NKV 4
#define HD  128

// Scratch (allocation-free rule: __device__ globals)
__device__ float g_q[B_*T_*NQ*HD];      // proj outputs (pre-rope fp32)
__device__ float g_k[B_*S_*NKV*HD];
__device__ float g_v[B_*S_*NKV*HD];
__device__ __align__(256) uint16_t g_qhi[B_*T_*NQ*HD];   // post-rope bf16 splits
__device__ __align__(256) uint16_t g_qlo[B_*T_*NQ*HD];
__device__ __align__(256) uint16_t g_khi[B_*S_*NKV*HD];
__device__ __align__(256) uint16_t g_klo[B_*S_*NKV*HD];
__device__ __align__(256) uint16_t g_vf [B_*S_*NKV*HD];  // v fp16
__device__ __align__(256) uint16_t g_attn_h[B_*T_*NQ*HD];

// ---------------------------------------------------------------------------
// helpers
// ---------------------------------------------------------------------------
__device__ __forceinline__ void mma_bf16(float d[4], const uint32_t a[4], const uint32_t b[2]) {
    asm volatile(
        "mma.sync.aligned.m16n8k16.row.col.f32.bf16.bf16.f32 "
        "{%0,%1,%2,%3}, {%4,%5,%6,%7}, {%8,%9}, {%0,%1,%2,%3};\n"
        : "+f"(d[0]), "+f"(d[1]), "+f"(d[2]), "+f"(d[3])
        : "r"(a[0]), "r"(a[1]), "r"(a[2]), "r"(a[3]), "r"(b[0]), "r"(b[1]));
}
__device__ __forceinline__ void mma_fp16(float d[4], const uint32_t a[4], const uint32_t b[2]) {
    asm volatile(
        "mma.sync.aligned.m16n8k16.row.col.f32.f16.f16.f32 "
        "{%0,%1,%2,%3}, {%4,%5,%6,%7}, {%8,%9}, {%0,%1,%2,%3};\n"
        : "+f"(d[0]), "+f"(d[1]), "+f"(d[2]), "+f"(d[3])
        : "r"(a[0]), "r"(a[1]), "r"(a[2]), "r"(a[3]), "r"(b[0]), "r"(b[1]));
}
__device__ __forceinline__ void ldsm_x4(uint32_t r[4], uint32_t addr) {
    asm volatile("ldmatrix.sync.aligned.m8n8.x4.shared.b16 {%0,%1,%2,%3}, [%4];"
                 : "=r"(r[0]), "=r"(r[1]), "=r"(r[2]), "=r"(r[3]) : "r"(addr));
}
__device__ __forceinline__ void ldsm_x4t(uint32_t r[4], uint32_t addr) {
    asm volatile("ldmatrix.sync.aligned.m8n8.x4.trans.shared.b16 {%0,%1,%2,%3}, [%4];"
                 : "=r"(r[0]), "=r"(r[1]), "=r"(r[2]), "=r"(r[3]) : "r"(addr));
}
__device__ __forceinline__ void ldsm_x2t(uint32_t r[2], uint32_t addr) {
    asm volatile("ldmatrix.sync.aligned.m8n8.x2.trans.shared.b16 {%0,%1}, [%2];"
                 : "=r"(r[0]), "=r"(r[1]) : "r"(addr));
}
__device__ __forceinline__ void bf16_split2(float x, float y, uint32_t& hi, uint32_t& lo) {
    __nv_bfloat16 hx = __float2bfloat16(x);
    __nv_bfloat16 hy = __float2bfloat16(y);
    __nv_bfloat16 lx = __float2bfloat16(x - __bfloat162float(hx));
    __nv_bfloat16 ly = __float2bfloat16(y - __bfloat162float(hy));
    hi = (uint32_t)__bfloat16_as_ushort(hx) | ((uint32_t)__bfloat16_as_ushort(hy) << 16);
    lo = (uint32_t)__bfloat16_as_ushort(lx) | ((uint32_t)__bfloat16_as_ushort(ly) << 16);
}
__device__ __forceinline__ void bf16_split1(float x, uint16_t& h, uint16_t& l) {
    __nv_bfloat16 hb = __float2bfloat16(x);
    h = __bfloat16_as_ushort(hb);
    l = __bfloat16_as_ushort(__float2bfloat16(x - __bfloat162float(hb)));
}
__device__ __forceinline__ uint32_t fp16_pack2(float x, float y) {
    __half2 h = __floats2half2_rn(x, y);
    return *(uint32_t*)&h;
}

// ---------------------------------------------------------------------------
// GEMM core (R13-exact, single-buffer): C[M,N] = A[M,K] @ B[K,N], CTA 128x128,
// BK=32, 8 warps 2x4. PASSES=3: bf16 3-term split. PASSES=1: fp16.
// X4T=1 only in bf3-free kernels (regalloc rule).
// ---------------------------------------------------------------------------
template<int PASSES, int X4T>
__device__ __forceinline__ void gemm_core(
    const float* __restrict__ A, const float* __restrict__ Bm, float* __restrict__ C,
    int N, int K, int row0, int col0, char* smraw)
{
    const uint32_t sb = (uint32_t)__cvta_generic_to_shared(smraw);
    constexpr int AHo = 0;
    constexpr int ALo = 10240;
    constexpr int BHo = (PASSES == 3) ? 20480 : 10240;
    constexpr int BLo = 29184;

    const int tid  = threadIdx.x;
    const int lane = tid & 31;
    const int warp = tid >> 5;
    const int grp  = lane >> 2;
    const int qid  = lane & 3;
    const int wm   = (warp >> 2) * 64;
    const int wn   = (warp & 3) * 32;

    float acc[4][4][4];
    #pragma unroll
    for (int i = 0; i < 4; i++)
        #pragma unroll
        for (int j = 0; j < 4; j++)
            #pragma unroll
            for (int c = 0; c < 4; c++) acc[i][j][c] = 0.f;

    float4 aReg[4], bReg[4];
    #pragma unroll
    for (int i = 0; i < 4; i++) {
        int idx = tid + i * 256;
        int ar = idx >> 3, ac = (idx & 7) << 2;
        aReg[i] = *(const float4*)(A + (size_t)(row0 + ar) * K + ac);
        int bk = idx >> 5, bn = (idx & 31) << 2;
        bReg[i] = *(const float4*)(Bm + (size_t)bk * N + col0 + bn);
    }

    for (int k0 = 0; k0 < K; k0 += 32) {
        #pragma unroll
        for (int i = 0; i < 4; i++) {
            int idx = tid + i * 256;
            int ar = idx >> 3, ac = (idx & 7) << 2;
            int aoff = (ar * 40 + ac) << 1;
            int bk = idx >> 5, bn = (idx & 31) << 2;
            int boff = (bk * 136 + bn) << 1;
            if (PASSES == 3) {
                uint32_t h01, l01, h23, l23;
                bf16_split2(aReg[i].x, aReg[i].y, h01, l01);
                bf16_split2(aReg[i].z, aReg[i].w, h23, l23);
                *(uint2*)(smraw + AHo + aoff) = make_uint2(h01, h23);
                *(uint2*)(smraw + ALo + aoff) = make_uint2(l01, l23);
                bf16_split2(bReg[i].x, bReg[i].y, h01, l01);
                bf16_split2(bReg[i].z, bReg[i].w, h23, l23);
                *(uint2*)(smraw + BHo + boff) = make_uint2(h01, h23);
                *(uint2*)(smraw + BLo + boff) = make_uint2(l01, l23);
            } else {
                *(uint2*)(smraw + AHo + aoff) =
                    make_uint2(fp16_pack2(aReg[i].x, aReg[i].y), fp16_pack2(aReg[i].z, aReg[i].w));
                *(uint2*)(smraw + BHo + boff) =
                    make_uint2(fp16_pack2(bReg[i].x, bReg[i].y), fp16_pack2(bReg[i].z, bReg[i].w));
            }
        }
        __syncthreads();

        if (k0 + 32 < K) {
            #pragma unroll
            for (int i = 0; i < 4; i++) {
                int idx = tid + i * 256;
                int ar = idx >> 3, ac = (idx & 7) << 2;
                aReg[i] = *(const float4*)(A + (size_t)(row0 + ar) * K + k0 + 32 + ac);
                int bk = idx >> 5, bn = (idx & 31) << 2;
                bReg[i] = *(const float4*)(Bm + (size_t)(k0 + 32 + bk) * N + col0 + bn);
            }
        }

        #pragma unroll
        for (int kk = 0; kk < 32; kk += 16) {
            uint32_t ah[4][4], al[4][4];
            #pragma unroll
            for (int im = 0; im < 4; im++) {
                int m = wm + im * 16 + (lane & 15);
                uint32_t ab = sb + AHo + ((m * 40 + kk + ((lane >> 4) << 3)) << 1);
                ldsm_x4(ah[im], ab);
                if (PASSES == 3) ldsm_x4(al[im], ab + (ALo - AHo));
            }
            uint32_t bh[4][2], bl[4][2];
            if (X4T) {
                #pragma unroll
                for (int pr = 0; pr < 2; pr++) {
                    int kr = kk + (lane & 15);
                    uint32_t bb = sb + BHo + ((kr * 136 + wn + pr * 16 + ((lane >> 4) << 3)) << 1);
                    uint32_t t4[4];
                    ldsm_x4t(t4, bb);
                    bh[2*pr][0] = t4[0]; bh[2*pr][1] = t4[1];
                    bh[2*pr+1][0] = t4[2]; bh[2*pr+1][1] = t4[3];
                    if (PASSES == 3) {
                        ldsm_x4t(t4, bb + (BLo - BHo));
                        bl[2*pr][0] = t4[0]; bl[2*pr][1] = t4[1];
                        bl[2*pr+1][0] = t4[2]; bl[2*pr+1][1] = t4[3];
                    }
                }
            } else {
                #pragma unroll
                for (int in_ = 0; in_ < 4; in_++) {
                    int kr = kk + (lane & 15);
                    uint32_t bb = sb + BHo + ((kr * 136 + wn + in_ * 8) << 1);
                    ldsm_x2t(bh[in_], bb);
                    if (PASSES == 3) ldsm_x2t(bl[in_], bb + (BLo - BHo));
                }
            }
            #pragma unroll
            for (int im = 0; im < 4; im++)
                #pragma unroll
                for (int in_ = 0; in_ < 4; in_++) {
                    if (PASSES == 3) {
                        mma_bf16(acc[im][in_], ah[im], bh[in_]);
                        mma_bf16(acc[im][in_], ah[im], bl[in_]);
                        mma_bf16(acc[im][in_], al[im], bh[in_]);
                    } else {
                        mma_fp16(acc[im][in_], ah[im], bh[in_]);
                    }
                }
        }
        __syncthreads();
    }

    #pragma unroll
    for (int im = 0; im < 4; im++) {
        int r = row0 + wm + im * 16 + grp;
        #pragma unroll
        for (int in_ = 0; in_ < 4; in_++) {
            int nc = col0 + wn + in_ * 8 + 2 * qid;
            *(float2*)(C + (size_t)r * N + nc)       = make_float2(acc[im][in_][0], acc[im][in_][1]);
            *(float2*)(C + (size_t)(r + 8) * N + nc) = make_float2(acc[im][in_][2], acc[im][in_][3]);
        }
    }
}

// Merged Q/K/V projections, occ-2, all-x2t, single-buffer.
__global__ void __launch_bounds__(256, 2) proj_qkv(
    const float* __restrict__ Xq, const float* __restrict__ Wq, float* __restrict__ Cq,
    const float* __restrict__ Xkv, const float* __restrict__ Wk, float* __restrict__ Ck,
    const float* __restrict__ Wv, float* __restrict__ Cv)
{
    extern __shared__ char smraw[];
    const int bx = blockIdx.x;
    const int row0 = blockIdx.y * 128;
    if (bx < 16)
        gemm_core<3, 0>(Xq, Wq, Cq, 2048, 2048, row0, bx * 128, smraw);
    else if (bx < 20)
        gemm_core<3, 0>(Xkv, Wk, Ck, 512, 2048, row0, (bx - 16) * 128, smraw);
    else
        gemm_core<1, 0>(Xkv, Wv, Cv, 512, 2048, row0, (bx - 20) * 128, smraw);
}

// ---------------------------------------------------------------------------
// Output projection with fp16 A input (R15-exact).
// ---------------------------------------------------------------------------
__global__ void __launch_bounds__(256, 2) gemm_o(
    const uint16_t* __restrict__ A, const float* __restrict__ Bm, float* __restrict__ C)
{
    extern __shared__ char smraw[];
    const uint32_t sb = (uint32_t)__cvta_generic_to_shared(smraw);
    constexpr int AHo = 0;
    constexpr int BHo = 10240;
    const int N = 2048, K = 2048;

    const int tid  = threadIdx.x;
    const int lane = tid & 31;
    const int warp = tid >> 5;
    const int grp  = lane >> 2;
    const int qid  = lane & 3;
    const int wm   = (warp >> 2) * 64;
    const int wn   = (warp & 3) * 32;
    const int row0 = blockIdx.y * 128;
    const int col0 = blockIdx.x * 128;

    float acc[4][4][4];
    #pragma unroll
    for (int i = 0; i < 4; i++)
        #pragma unroll
        for (int j = 0; j < 4; j++)
            #pragma unroll
            for (int c = 0; c < 4; c++) acc[i][j][c] = 0.f;

    uint2 aReg[4];
    float4 bReg[4];
    #pragma unroll
    for (int i = 0; i < 4; i++) {
        int idx = tid + i * 256;
        int ar = idx >> 3, ac = (idx & 7) << 2;
        aReg[i] = *(const uint2*)(A + (size_t)(row0 + ar) * K + ac);
        int bk = idx >> 5, bn = (idx & 31) << 2;
        bReg[i] = *(const float4*)(Bm + (size_t)bk * N + col0 + bn);
    }

    for (int k0 = 0; k0 < K; k0 += 32) {
        #pragma unroll
        for (int i = 0; i < 4; i++) {
            int idx = tid + i * 256;
            int ar = idx >> 3, ac = (idx & 7) << 2;
            *(uint2*)(smraw + AHo + ((ar * 40 + ac) << 1)) = aReg[i];
            int bk = idx >> 5, bn = (idx & 31) << 2;
            *(uint2*)(smraw + BHo + ((bk * 136 + bn) << 1)) =
                make_uint2(fp16_pack2(bReg[i].x, bReg[i].y), fp16_pack2(bReg[i].z, bReg[i].w));
        }
        __syncthreads();

        if (k0 + 32 < K) {
            #pragma unroll
            for (int i = 0; i < 4; i++) {
                int idx = tid + i * 256;
                int ar = idx >> 3, ac = (idx & 7) << 2;
                aReg[i] = *(const uint2*)(A + (size_t)(row0 + ar) * K + k0 + 32 + ac);
                int bk = idx >> 5, bn = (idx & 31) << 2;
                bReg[i] = *(const float4*)(Bm + (size_t)(k0 + 32 + bk) * N + col0 + bn);
            }
        }

        #pragma unroll
        for (int kk = 0; kk < 32; kk += 16) {
            uint32_t ah[4][4];
            #pragma unroll
            for (int im = 0; im < 4; im++) {
                int m = wm + im * 16 + (lane & 15);
                ldsm_x4(ah[im], sb + AHo + ((m * 40 + kk + ((lane >> 4) << 3)) << 1));
            }
            uint32_t bh[4][2];
            #pragma unroll
            for (int pr = 0; pr < 2; pr++) {
                int kr = kk + (lane & 15);
                uint32_t t4[4];
                ldsm_x4t(t4, sb + BHo + ((kr * 136 + wn + pr * 16 + ((lane >> 4) << 3)) << 1));
                bh[2*pr][0] = t4[0]; bh[2*pr][1] = t4[1];
                bh[2*pr+1][0] = t4[2]; bh[2*pr+1][1] = t4[3];
            }
            #pragma unroll
            for (int im = 0; im < 4; im++)
                #pragma unroll
                for (int in_ = 0; in_ < 4; in_++)
                    mma_fp16(acc[im][in_], ah[im], bh[in_]);
        }
        __syncthreads();
    }

    #pragma unroll
    for (int im = 0; im < 4; im++) {
        int r = row0 + wm + im * 16 + grp;
        #pragma unroll
        for (int in_ = 0; in_ < 4; in_++) {
            int nc = col0 + wn + in_ * 8 + 2 * qid;
            *(float2*)(C + (size_t)r * N + nc)       = make_float2(acc[im][in_][0], acc[im][in_][1]);
            *(float2*)(C + (size_t)(r + 8) * N + nc) = make_float2(acc[im][in_][2], acc[im][in_][3]);
        }
    }
}

// ---------------------------------------------------------------------------
// prep: RoPE q -> qhi/qlo (bf16 split), RoPE k -> khi/klo, v -> fp16.
// Same math as R15 (exp2f RoPE + identical splits), relocated from attention.
// ---------------------------------------------------------------------------
#define QR (B_*T_*NQ*64)
#define KR (B_*S_*NKV*64)
#define VR (B_*S_*NKV*HD/4)

__global__ void prep_fused(const float* __restrict__ q, const float* __restrict__ k,
                           const float* __restrict__ v,
                           const int* __restrict__ qpos, const int* __restrict__ kpos,
                           uint16_t* __restrict__ qhi, uint16_t* __restrict__ qlo,
                           uint16_t* __restrict__ khi, uint16_t* __restrict__ klo,
                           uint16_t* __restrict__ vf)
{
    int idx = blockIdx.x * blockDim.x + threadIdx.x;
    if (idx < QR + KR) {
        const float* x; const int* pos; int Nh; uint16_t *oh, *ol;
        if (idx < QR) { x = q; pos = qpos; Nh = NQ; oh = qhi; ol = qlo; }
        else { idx -= QR; x = k; pos = kpos; Nh = NKV; oh = khi; ol = klo; }
        int i   = idx & 63;
        int bln = idx >> 6;
        int bl  = bln / Nh;
        float p    = (float)pos[bl];
        float frac = (float)i * (1.0f / 64.0f);
        float inv_ts = exp2f(frac * -13.287712379549449f);
        float ang  = p * inv_ts;
        float si = sinf(ang), co = cosf(ang);
        const float* base = x + (size_t)bln * HD;
        float x1 = base[i], x2 = base[i + 64];
        float y1 = x1 * co - x2 * si;
        float y2 = x2 * co + x1 * si;
        uint16_t h, l;
        size_t o0 = (size_t)bln * HD + i;
        bf16_split1(y1, h, l); oh[o0] = h;      ol[o0] = l;
        bf16_split1(y2, h, l); oh[o0 + 64] = h; ol[o0 + 64] = l;
    } else {
        int j = idx - QR - KR;
        if (j >= VR) return;
        float4 vv = ((const float4*)v)[j];
        ((uint2*)vf)[j] = make_uint2(fp16_pack2(vv.x, vv.y), fp16_pack2(vv.z, vv.w));
    }
}

// ---------------------------------------------------------------------------
// Flash attention: same structure/smem/occ-2 as R15, but fills are pure
// LDG.128 -> STS.128 from pre-converted 16-bit buffers (no cvt in-loop).
// Smem: QH 0 (34816), QL 34816, KH 69632 (8704), KL 78336, VS 87040 (8704).
// Total 95744 -> 2 CTAs/SM.
// ---------------------------------------------------------------------------
#define A_QH 0
#define A_QL 34816
#define A_KH 69632
#define A_KL 78336
#define A_VS 87040
#define A_SMEM 95744
#define VSH 136

__global__ void __launch_bounds__(256, 2) attn_tc_kernel(
    const uint16_t* __restrict__ qhi, const uint16_t* __restrict__ qlo,
    const uint16_t* __restrict__ khi, const uint16_t* __restrict__ klo,
    const uint16_t* __restrict__ vf, uint16_t* __restrict__ o)
{
    extern __shared__ char smraw[];
    const uint32_t sb = (uint32_t)__cvta_generic_to_shared(smraw);

    const int tid  = threadIdx.x;
    const int lane = tid & 31;
    const int warp = tid >> 5;
    const int grp  = lane >> 2;
    const int qid  = lane & 3;
    const int wm   = warp * 16;
    const int t0   = blockIdx.x * 128;
    const int n    = blockIdx.y;
    const int b    = blockIdx.z;
    const int kvh  = n >> 2;

    const uint16_t* Qh = qhi + ((size_t)(b * T_ + t0) * NQ  + n)   * HD;
    const uint16_t* Ql = qlo + ((size_t)(b * T_ + t0) * NQ  + n)   * HD;
    const uint16_t* Kh = khi + ((size_t)(b * S_)      * NKV + kvh) * HD;
    const uint16_t* Kl = klo + ((size_t)(b * S_)      * NKV + kvh) * HD;
    const uint16_t* Vf = vf  + ((size_t)(b * S_)      * NKV + kvh) * HD;

    // Q fill: 2 planes x 128 rows x 16 chunks of 8 halves -> pure LDG/STS
    #pragma unroll
    for (int it = 0; it < 16; it++) {
        int f = tid + it * 256;          // 0..4095
        int plane = f >> 11;
        int fi = f & 2047;
        int r = fi >> 4, c8 = (fi & 15) << 3;
        const uint16_t* src = (plane ? Ql : Qh) + (size_t)r * (NQ * HD) + c8;
        *(uint4*)(smraw + (plane ? A_QL : A_QH) + ((r * 136 + c8) << 1)) = *(const uint4*)src;
    }

    float m0 = -1e30f, m1 = -1e30f, l0 = 0.f, l1 = 0.f;
    float oacc[16][4];
    #pragma unroll
    for (int j = 0; j < 16; j++)
        #pragma unroll
        for (int c = 0; c < 4; c++) oacc[j][c] = 0.f;

    for (int blk = 0; blk < 32; blk++) {
        __syncthreads();
        {
            const int s0 = blk * 32;
            // 3 regions x 32 rows x 16 chunks of 8 halves = 1536 -> 6/thread
            #pragma unroll
            for (int it = 0; it < 6; it++) {
                int f = tid + it * 256;
                int region = f >> 9;
                int fi = f & 511;
                int r = fi >> 4, c8 = (fi & 15) << 3;
                const uint16_t* src = (region == 0 ? Kh : region == 1 ? Kl : Vf)
                                      + (size_t)(s0 + r) * (NKV * HD) + c8;
                int base = (region == 0) ? A_KH : (region == 1) ? A_KL : A_VS;
                *(uint4*)(smraw + base + ((r * 136 + c8) << 1)) = *(const uint4*)src;
            }
        }
        __syncthreads();

        float sacc[4][4];
        #pragma unroll
        for (int j = 0; j < 4; j++)
            #pragma unroll
            for (int c = 0; c < 4; c++) sacc[j][c] = 0.f;

        #pragma unroll
        for (int kk = 0; kk < 8; kk++) {
            const int col0h = kk * 16;
            uint32_t ah[4], al[4];
            {
                int m = wm + (lane & 15);
                uint32_t ab = sb + A_QH + ((m * 136 + col0h + ((lane >> 4) << 3)) << 1);
                ldsm_x4(ah, ab);
                ldsm_x4(al, ab + (A_QL - A_QH));
            }
            #pragma unroll
            for (int j2 = 0; j2 < 2; j2++) {
                int row = (j2 * 2 + (lane >> 4)) * 8 + (lane & 7);
                uint32_t bb = sb + A_KH + ((row * 136 + col0h + (lane & 8)) << 1);
                uint32_t bh4[4], bl4[4];
                ldsm_x4(bh4, bb);
                ldsm_x4(bl4, bb + (A_KL - A_KH));
                mma_bf16(sacc[2*j2],   ah, bh4);
                mma_bf16(sacc[2*j2],   ah, bl4);
                mma_bf16(sacc[2*j2],   al, bh4);
                mma_bf16(sacc[2*j2+1], ah, bh4 + 2);
                mma_bf16(sacc[2*j2+1], ah, bl4 + 2);
                mma_bf16(sacc[2*j2+1], al, bh4 + 2);
            }
        }

        float mx0 = -1e30f, mx1 = -1e30f;
        #pragma unroll
        for (int j = 0; j < 4; j++) {
            mx0 = fmaxf(mx0, fmaxf(sacc[j][0], sacc[j][1]));
            mx1 = fmaxf(mx1, fmaxf(sacc[j][2], sacc[j][3]));
        }
        #pragma unroll
        for (int off = 1; off < 4; off <<= 1) {
            mx0 = fmaxf(mx0, __shfl_xor_sync(0xffffffffu, mx0, off));
            mx1 = fmaxf(mx1, __shfl_xor_sync(0xffffffffu, mx1, off));
        }
        float mn0 = fmaxf(m0, mx0), mn1 = fmaxf(m1, mx1);
        float cr0 = __expf(m0 - mn0), cr1 = __expf(m1 - mn1);
        float ps0 = 0.f, ps1 = 0.f;
        uint32_t pk[4][2];
        #pragma unroll
        for (int j = 0; j < 4; j++) {
            float e0 = __expf(sacc[j][0] - mn0);
            float e1 = __expf(sacc[j][1] - mn0);
            float e2 = __expf(sacc[j][2] - mn1);
            float e3 = __expf(sacc[j][3] - mn1);
            ps0 += e0 + e1; ps1 += e2 + e3;
            pk[j][0] = fp16_pack2(e0, e1);
            pk[j][1] = fp16_pack2(e2, e3);
        }
        #pragma unroll
        for (int off = 1; off < 4; off <<= 1) {
            ps0 += __shfl_xor_sync(0xffffffffu, ps0, off);
            ps1 += __shfl_xor_sync(0xffffffffu, ps1, off);
        }
        l0 = l0 * cr0 + ps0; m0 = mn0;
        l1 = l1 * cr1 + ps1; m1 = mn1;
        #pragma unroll
        for (int j = 0; j < 16; j++) {
            oacc[j][0] *= cr0; oacc[j][1] *= cr0;
            oacc[j][2] *= cr1; oacc[j][3] *= cr1;
        }

        #pragma unroll
        for (int kk2 = 0; kk2 < 2; kk2++) {
            uint32_t pa[4] = { pk[2*kk2][0], pk[2*kk2][1], pk[2*kk2+1][0], pk[2*kk2+1][1] };
            #pragma unroll
            for (int j2 = 0; j2 < 8; j2++) {
                int kr  = kk2 * 16 + (lane & 15);
                int col = (j2 * 2 + (lane >> 4)) * 8;
                uint32_t vb4[4];
                ldsm_x4t(vb4, sb + A_VS + ((kr * VSH + col) << 1));
                mma_fp16(oacc[2*j2],     pa, vb4);
                mma_fp16(oacc[2*j2 + 1], pa, vb4 + 2);
            }
        }
    }

    float inv0 = 1.0f / l0, inv1 = 1.0f / l1;
    uint16_t* o0 = o + ((size_t)(b * T_ + t0 + wm + grp)     * NQ + n) * HD;
    uint16_t* o1 = o + ((size_t)(b * T_ + t0 + wm + grp + 8) * NQ + n) * HD;
    #pragma unroll
    for (int j = 0; j < 16; j++) {
        int col = j * 8 + 2 * qid;
        *(uint32_t*)(o0 + col) = fp16_pack2(oacc[j][0] * inv0, oacc[j][1] * inv0);
        *(uint32_t*)(o1 + col) = fp16_pack2(oacc[j][2] * inv1, oacc[j][3] * inv1);
    }
}

// ---------------- Launch ----------------
extern "C" void kernel_launch(void* const* d_in, const int* in_sizes, int n_in,
                              void* d_out, int out_size)
{
    const float* Xq  = (const float*)d_in[0];
    const float* Xkv = (const float*)d_in[1];
    const int*   qpos = (const int*)d_in[2];
    const int*   kpos = (const int*)d_in[3];
    const float* Wq  = (const float*)d_in[4];
    const float* Wk  = (const float*)d_in[5];
    const float* Wv  = (const float*)d_in[6];
    const float* Wo  = (const float*)d_in[7];
    float* out = (float*)d_out;

    float *qb, *kb, *vb;
    uint16_t *qh, *ql, *kh, *kl, *vfp, *ah;
    cudaGetSymbolAddress((void**)&qb, g_q);
    cudaGetSymbolAddress((void**)&kb, g_k);
    cudaGetSymbolAddress((void**)&vb, g_v);
    cudaGetSymbolAddress((void**)&qh, g_qhi);
    cudaGetSymbolAddress((void**)&ql, g_qlo);
    cudaGetSymbolAddress((void**)&kh, g_khi);
    cudaGetSymbolAddress((void**)&kl, g_klo);
    cudaGetSymbolAddress((void**)&vfp, g_vf);
    cudaGetSymbolAddress((void**)&ah, g_attn_h);

    const int P_SMEM = 37888;
    const int O_SMEM = 18944;
    cudaFuncSetAttribute(proj_qkv, cudaFuncAttributeMaxDynamicSharedMemorySize, P_SMEM);
    cudaFuncSetAttribute(gemm_o, cudaFuncAttributeMaxDynamicSharedMemorySize, O_SMEM);
    cudaFuncSetAttribute(attn_tc_kernel, cudaFuncAttributeMaxDynamicSharedMemorySize, A_SMEM);

    // Q/K/V projections in one launch (R13-exact)
    proj_qkv<<<dim3(24, 16), 256, P_SMEM>>>(Xq, Wq, qb, Xkv, Wk, kb, Wv, vb);

    // RoPE + split/convert to 16-bit operand buffers, one launch
    prep_fused<<<(QR + KR + VR + 255) / 256, 256>>>(qb, kb, vb, qpos, kpos,
                                                    qh, ql, kh, kl, vfp);

    // Attention (R15 structure; pure LDG/STS fills, occ-2)
    attn_tc_kernel<<<dim3(T_/128, NQ, B_), 256, A_SMEM>>>(qh, ql, kh, kl, vfp, ah);

    // Output projection (fp16 A input, occ-2, x4t)
    gemm_o<<<dim3(16, 16), 256, O_SMEM>>>(ah, Wo, out);
}

// round 17
// speedup vs baseline: 1.1235x; 1.0137x over previous
#include <cuda_runtime.h>
#include <cuda_bf16.h>
#include <cuda_fp16.h>
#include <cstdint>

#define B_  2
#define T_  1024
#define S_  1024
#define NQ  16
#define NKV 4
#define HD  128

// 16-bit attention operands (written directly by proj epilogues)
__device__ __align__(256) uint16_t g_qhi[B_*T_*NQ*HD];
__device__ __align__(256) uint16_t g_qlo[B_*T_*NQ*HD];
__device__ __align__(256) uint16_t g_khi[B_*S_*NKV*HD];
__device__ __align__(256) uint16_t g_klo[B_*S_*NKV*HD];
__device__ __align__(256) uint16_t g_vf [B_*S_*NKV*HD];
__device__ __align__(256) uint16_t g_attn_h[B_*T_*NQ*HD];

// ---------------------------------------------------------------------------
// helpers
// ---------------------------------------------------------------------------
__device__ __forceinline__ void mma_bf16(float d[4], const uint32_t a[4], const uint32_t b[2]) {
    asm volatile(
        "mma.sync.aligned.m16n8k16.row.col.f32.bf16.bf16.f32 "
        "{%0,%1,%2,%3}, {%4,%5,%6,%7}, {%8,%9}, {%0,%1,%2,%3};\n"
        : "+f"(d[0]), "+f"(d[1]), "+f"(d[2]), "+f"(d[3])
        : "r"(a[0]), "r"(a[1]), "r"(a[2]), "r"(a[3]), "r"(b[0]), "r"(b[1]));
}
__device__ __forceinline__ void mma_fp16(float d[4], const uint32_t a[4], const uint32_t b[2]) {
    asm volatile(
        "mma.sync.aligned.m16n8k16.row.col.f32.f16.f16.f32 "
        "{%0,%1,%2,%3}, {%4,%5,%6,%7}, {%8,%9}, {%0,%1,%2,%3};\n"
        : "+f"(d[0]), "+f"(d[1]), "+f"(d[2]), "+f"(d[3])
        : "r"(a[0]), "r"(a[1]), "r"(a[2]), "r"(a[3]), "r"(b[0]), "r"(b[1]));
}
__device__ __forceinline__ void ldsm_x4(uint32_t r[4], uint32_t addr) {
    asm volatile("ldmatrix.sync.aligned.m8n8.x4.shared.b16 {%0,%1,%2,%3}, [%4];"
                 : "=r"(r[0]), "=r"(r[1]), "=r"(r[2]), "=r"(r[3]) : "r"(addr));
}
__device__ __forceinline__ void ldsm_x4t(uint32_t r[4], uint32_t addr) {
    asm volatile("ldmatrix.sync.aligned.m8n8.x4.trans.shared.b16 {%0,%1,%2,%3}, [%4];"
                 : "=r"(r[0]), "=r"(r[1]), "=r"(r[2]), "=r"(r[3]) : "r"(addr));
}
__device__ __forceinline__ void ldsm_x2t(uint32_t r[2], uint32_t addr) {
    asm volatile("ldmatrix.sync.aligned.m8n8.x2.trans.shared.b16 {%0,%1}, [%2];"
                 : "=r"(r[0]), "=r"(r[1]) : "r"(addr));
}
__device__ __forceinline__ void bf16_split2(float x, float y, uint32_t& hi, uint32_t& lo) {
    __nv_bfloat16 hx = __float2bfloat16(x);
    __nv_bfloat16 hy = __float2bfloat16(y);
    __nv_bfloat16 lx = __float2bfloat16(x - __bfloat162float(hx));
    __nv_bfloat16 ly = __float2bfloat16(y - __bfloat162float(hy));
    hi = (uint32_t)__bfloat16_as_ushort(hx) | ((uint32_t)__bfloat16_as_ushort(hy) << 16);
    lo = (uint32_t)__bfloat16_as_ushort(lx) | ((uint32_t)__bfloat16_as_ushort(ly) << 16);
}
__device__ __forceinline__ void bf16_split1(float x, uint16_t& h, uint16_t& l) {
    __nv_bfloat16 hb = __float2bfloat16(x);
    h = __bfloat16_as_ushort(hb);
    l = __bfloat16_as_ushort(__float2bfloat16(x - __bfloat162float(hb)));
}
__device__ __forceinline__ uint32_t fp16_pack2(float x, float y) {
    __half2 h = __floats2half2_rn(x, y);
    return *(uint32_t*)&h;
}

// ---------------------------------------------------------------------------
// GEMM main loop only (R13/R16-exact structure, x2t B gather — proj-safe):
// acc[4][4][4] returned in registers. CTA 128x128, BK=32, 8 warps 2x4.
// PASSES=3: bf16 hi/lo 3-term split. PASSES=1: 1-pass fp16.
// ---------------------------------------------------------------------------
template<int PASSES>
__device__ __forceinline__ void gemm_main(
    const float* __restrict__ A, const float* __restrict__ Bm,
    int N, int K, int row0, int col0, char* smraw, float acc[4][4][4])
{
    const uint32_t sb = (uint32_t)__cvta_generic_to_shared(smraw);
    constexpr int AHo = 0;
    constexpr int ALo = 10240;
    constexpr int BHo = (PASSES == 3) ? 20480 : 10240;
    constexpr int BLo = 29184;

    const int tid  = threadIdx.x;
    const int lane = tid & 31;
    const int warp = tid >> 5;
    const int wm   = (warp >> 2) * 64;
    const int wn   = (warp & 3) * 32;

    #pragma unroll
    for (int i = 0; i < 4; i++)
        #pragma unroll
        for (int j = 0; j < 4; j++)
            #pragma unroll
            for (int c = 0; c < 4; c++) acc[i][j][c] = 0.f;

    float4 aReg[4], bReg[4];
    #pragma unroll
    for (int i = 0; i < 4; i++) {
        int idx = tid + i * 256;
        int ar = idx >> 3, ac = (idx & 7) << 2;
        aReg[i] = *(const float4*)(A + (size_t)(row0 + ar) * K + ac);
        int bk = idx >> 5, bn = (idx & 31) << 2;
        bReg[i] = *(const float4*)(Bm + (size_t)bk * N + col0 + bn);
    }

    for (int k0 = 0; k0 < K; k0 += 32) {
        #pragma unroll
        for (int i = 0; i < 4; i++) {
            int idx = tid + i * 256;
            int ar = idx >> 3, ac = (idx & 7) << 2;
            int aoff = (ar * 40 + ac) << 1;
            int bk = idx >> 5, bn = (idx & 31) << 2;
            int boff = (bk * 136 + bn) << 1;
            if (PASSES == 3) {
                uint32_t h01, l01, h23, l23;
                bf16_split2(aReg[i].x, aReg[i].y, h01, l01);
                bf16_split2(aReg[i].z, aReg[i].w, h23, l23);
                *(uint2*)(smraw + AHo + aoff) = make_uint2(h01, h23);
                *(uint2*)(smraw + ALo + aoff) = make_uint2(l01, l23);
                bf16_split2(bReg[i].x, bReg[i].y, h01, l01);
                bf16_split2(bReg[i].z, bReg[i].w, h23, l23);
                *(uint2*)(smraw + BHo + boff) = make_uint2(h01, h23);
                *(uint2*)(smraw + BLo + boff) = make_uint2(l01, l23);
            } else {
                *(uint2*)(smraw + AHo + aoff) =
                    make_uint2(fp16_pack2(aReg[i].x, aReg[i].y), fp16_pack2(aReg[i].z, aReg[i].w));
                *(uint2*)(smraw + BHo + boff) =
                    make_uint2(fp16_pack2(bReg[i].x, bReg[i].y), fp16_pack2(bReg[i].z, bReg[i].w));
            }
        }
        __syncthreads();

        if (k0 + 32 < K) {
            #pragma unroll
            for (int i = 0; i < 4; i++) {
                int idx = tid + i * 256;
                int ar = idx >> 3, ac = (idx & 7) << 2;
                aReg[i] = *(const float4*)(A + (size_t)(row0 + ar) * K + k0 + 32 + ac);
                int bk = idx >> 5, bn = (idx & 31) << 2;
                bReg[i] = *(const float4*)(Bm + (size_t)(k0 + 32 + bk) * N + col0 + bn);
            }
        }

        #pragma unroll
        for (int kk = 0; kk < 32; kk += 16) {
            uint32_t ah[4][4], al[4][4];
            #pragma unroll
            for (int im = 0; im < 4; im++) {
                int m = wm + im * 16 + (lane & 15);
                uint32_t ab = sb + AHo + ((m * 40 + kk + ((lane >> 4) << 3)) << 1);
                ldsm_x4(ah[im], ab);
                if (PASSES == 3) ldsm_x4(al[im], ab + (ALo - AHo));
            }
            uint32_t bh[4][2], bl[4][2];
            #pragma unroll
            for (int in_ = 0; in_ < 4; in_++) {
                int kr = kk + (lane & 15);
                uint32_t bb = sb + BHo + ((kr * 136 + wn + in_ * 8) << 1);
                ldsm_x2t(bh[in_], bb);
                if (PASSES == 3) ldsm_x2t(bl[in_], bb + (BLo - BHo));
            }
            #pragma unroll
            for (int im = 0; im < 4; im++)
                #pragma unroll
                for (int in_ = 0; in_ < 4; in_++) {
                    if (PASSES == 3) {
                        mma_bf16(acc[im][in_], ah[im], bh[in_]);
                        mma_bf16(acc[im][in_], ah[im], bl[in_]);
                        mma_bf16(acc[im][in_], al[im], bh[in_]);
                    } else {
                        mma_fp16(acc[im][in_], ah[im], bh[in_]);
                    }
                }
        }
        __syncthreads();
    }
}

// ---------------------------------------------------------------------------
// Merged Q/K/V projections with fused RoPE-split epilogue (prep eliminated).
// Q/K: stage acc fp32 to smem [128][132], RoPE pairs (h, h+64), bf16 split,
// write qhi/qlo/khi/klo. V: pack fp16 directly. occ-2, all-x2t, single-buffer.
// Smem = max(37888 main, 67584 epilogue stage) = 67584.
// ---------------------------------------------------------------------------
__global__ void __launch_bounds__(256, 2) proj_qkv(
    const float* __restrict__ Xq, const float* __restrict__ Wq,
    const float* __restrict__ Xkv, const float* __restrict__ Wk,
    const float* __restrict__ Wv,
    const int* __restrict__ qpos, const int* __restrict__ kpos,
    uint16_t* __restrict__ qhi, uint16_t* __restrict__ qlo,
    uint16_t* __restrict__ khi, uint16_t* __restrict__ klo,
    uint16_t* __restrict__ vf)
{
    extern __shared__ char smraw[];
    const int bx   = blockIdx.x;
    const int row0 = blockIdx.y * 128;
    const int tid  = threadIdx.x;
    const int lane = tid & 31;
    const int warp = tid >> 5;
    const int grp  = lane >> 2;
    const int qid  = lane & 3;
    const int wm   = (warp >> 2) * 64;
    const int wn   = (warp & 3) * 32;

    float acc[4][4][4];

    if (bx < 20) {
        // ---- bf16-3x GEMM: Q (bx<16) or K (16<=bx<20) ----
        const bool isQ = (bx < 16);
        const float* A  = isQ ? Xq : Xkv;
        const float* Bm = isQ ? Wq : Wk;
        const int N     = isQ ? 2048 : 512;
        const int col0  = (isQ ? bx : bx - 16) * 128;
        gemm_main<3>(A, Bm, N, 2048, row0, col0, smraw, acc);

        uint16_t* ohi   = isQ ? qhi : khi;
        uint16_t* olo   = isQ ? qlo : klo;
        const int* pos  = isQ ? qpos : kpos;
        const int NH    = isQ ? NQ : NKV;
        const int n     = col0 >> 7;

        // stage acc tile to smem fp32 (main loop ended with __syncthreads)
        float* st = (float*)smraw;
        #pragma unroll
        for (int im = 0; im < 4; im++) {
            int r = wm + im * 16 + grp;
            #pragma unroll
            for (int in_ = 0; in_ < 4; in_++) {
                int c = wn + in_ * 8 + 2 * qid;
                *(float2*)&st[r * 132 + c]       = make_float2(acc[im][in_][0], acc[im][in_][1]);
                *(float2*)&st[(r + 8) * 132 + c] = make_float2(acc[im][in_][2], acc[im][in_][3]);
            }
        }
        __syncthreads();

        // RoPE + bf16 split, write 16-bit operand buffers
        for (int f = tid; f < 128 * 64; f += 256) {
            int r = f >> 6, i = f & 63;
            int bt = row0 + r;
            float p    = (float)pos[bt];
            float frac = (float)i * (1.0f / 64.0f);
            float ang  = p * exp2f(frac * -13.287712379549449f);
            float si = sinf(ang), co = cosf(ang);
            float x1 = st[r * 132 + i], x2 = st[r * 132 + i + 64];
            float y1 = x1 * co - x2 * si;
            float y2 = x2 * co + x1 * si;
            uint16_t h, l;
            size_t o0 = ((size_t)bt * NH + n) * HD + i;
            bf16_split1(y1, h, l); ohi[o0] = h;      olo[o0] = l;
            bf16_split1(y2, h, l); ohi[o0 + 64] = h; olo[o0 + 64] = l;
        }
    } else {
        // ---- fp16 GEMM: V ----
        const int col0 = (bx - 20) * 128;
        gemm_main<1>(Xkv, Wv, 512, 2048, row0, col0, smraw, acc);
        const int n = col0 >> 7;
        #pragma unroll
        for (int im = 0; im < 4; im++) {
            int r = row0 + wm + im * 16 + grp;
            #pragma unroll
            for (int in_ = 0; in_ < 4; in_++) {
                int nc = wn + in_ * 8 + 2 * qid;
                *(uint32_t*)(vf + ((size_t)r * NKV + n) * HD + nc) =
                    fp16_pack2(acc[im][in_][0], acc[im][in_][1]);
                *(uint32_t*)(vf + ((size_t)(r + 8) * NKV + n) * HD + nc) =
                    fp16_pack2(acc[im][in_][2], acc[im][in_][3]);
            }
        }
    }
}

// ---------------------------------------------------------------------------
// Output projection with fp16 A input (R15/R16-exact): standalone, x4t, occ-2.
// ---------------------------------------------------------------------------
__global__ void __launch_bounds__(256, 2) gemm_o(
    const uint16_t* __restrict__ A, const float* __restrict__ Bm, float* __restrict__ C)
{
    extern __shared__ char smraw[];
    const uint32_t sb = (uint32_t)__cvta_generic_to_shared(smraw);
    constexpr int AHo = 0;
    constexpr int BHo = 10240;
    const int N = 2048, K = 2048;

    const int tid  = threadIdx.x;
    const int lane = tid & 31;
    const int warp = tid >> 5;
    const int grp  = lane >> 2;
    const int qid  = lane & 3;
    const int wm   = (warp >> 2) * 64;
    const int wn   = (warp & 3) * 32;
    const int row0 = blockIdx.y * 128;
    const int col0 = blockIdx.x * 128;

    float acc[4][4][4];
    #pragma unroll
    for (int i = 0; i < 4; i++)
        #pragma unroll
        for (int j = 0; j < 4; j++)
            #pragma unroll
            for (int c = 0; c < 4; c++) acc[i][j][c] = 0.f;

    uint2 aReg[4];
    float4 bReg[4];
    #pragma unroll
    for (int i = 0; i < 4; i++) {
        int idx = tid + i * 256;
        int ar = idx >> 3, ac = (idx & 7) << 2;
        aReg[i] = *(const uint2*)(A + (size_t)(row0 + ar) * K + ac);
        int bk = idx >> 5, bn = (idx & 31) << 2;
        bReg[i] = *(const float4*)(Bm + (size_t)bk * N + col0 + bn);
    }

    for (int k0 = 0; k0 < K; k0 += 32) {
        #pragma unroll
        for (int i = 0; i < 4; i++) {
            int idx = tid + i * 256;
            int ar = idx >> 3, ac = (idx & 7) << 2;
            *(uint2*)(smraw + AHo + ((ar * 40 + ac) << 1)) = aReg[i];
            int bk = idx >> 5, bn = (idx & 31) << 2;
            *(uint2*)(smraw + BHo + ((bk * 136 + bn) << 1)) =
                make_uint2(fp16_pack2(bReg[i].x, bReg[i].y), fp16_pack2(bReg[i].z, bReg[i].w));
        }
        __syncthreads();

        if (k0 + 32 < K) {
            #pragma unroll
            for (int i = 0; i < 4; i++) {
                int idx = tid + i * 256;
                int ar = idx >> 3, ac = (idx & 7) << 2;
                aReg[i] = *(const uint2*)(A + (size_t)(row0 + ar) * K + k0 + 32 + ac);
                int bk = idx >> 5, bn = (idx & 31) << 2;
                bReg[i] = *(const float4*)(Bm + (size_t)(k0 + 32 + bk) * N + col0 + bn);
            }
        }

        #pragma unroll
        for (int kk = 0; kk < 32; kk += 16) {
            uint32_t ah[4][4];
            #pragma unroll
            for (int im = 0; im < 4; im++) {
                int m = wm + im * 16 + (lane & 15);
                ldsm_x4(ah[im], sb + AHo + ((m * 40 + kk + ((lane >> 4) << 3)) << 1));
            }
            uint32_t bh[4][2];
            #pragma unroll
            for (int pr = 0; pr < 2; pr++) {
                int kr = kk + (lane & 15);
                uint32_t t4[4];
                ldsm_x4t(t4, sb + BHo + ((kr * 136 + wn + pr * 16 + ((lane >> 4) << 3)) << 1));
                bh[2*pr][0] = t4[0]; bh[2*pr][1] = t4[1];
                bh[2*pr+1][0] = t4[2]; bh[2*pr+1][1] = t4[3];
            }
            #pragma unroll
            for (int im = 0; im < 4; im++)
                #pragma unroll
                for (int in_ = 0; in_ < 4; in_++)
                    mma_fp16(acc[im][in_], ah[im], bh[in_]);
        }
        __syncthreads();
    }

    #pragma unroll
    for (int im = 0; im < 4; im++) {
        int r = row0 + wm + im * 16 + grp;
        #pragma unroll
        for (int in_ = 0; in_ < 4; in_++) {
            int nc = col0 + wn + in_ * 8 + 2 * qid;
            *(float2*)(C + (size_t)r * N + nc)       = make_float2(acc[im][in_][0], acc[im][in_][1]);
            *(float2*)(C + (size_t)(r + 8) * N + nc) = make_float2(acc[im][in_][2], acc[im][in_][3]);
        }
    }
}

// ---------------------------------------------------------------------------
// Flash attention (R16-exact): occ-2, KV block 32, pure LDG/STS fills from
// pre-converted 16-bit buffers, bf16-3x QK^T, fp16 PV from registers.
// Smem: QH 0 (34816), QL 34816, KH 69632 (8704), KL 78336, VS 87040 (8704).
// Total 95744 -> 2 CTAs/SM.
// ---------------------------------------------------------------------------
#define A_QH 0
#define A_QL 34816
#define A_KH 69632
#define A_KL 78336
#define A_VS 87040
#define A_SMEM 95744
#define VSH 136

__global__ void __launch_bounds__(256, 2) attn_tc_kernel(
    const uint16_t* __restrict__ qhi, const uint16_t* __restrict__ qlo,
    const uint16_t* __restrict__ khi, const uint16_t* __restrict__ klo,
    const uint16_t* __restrict__ vf, uint16_t* __restrict__ o)
{
    extern __shared__ char smraw[];
    const uint32_t sb = (uint32_t)__cvta_generic_to_shared(smraw);

    const int tid  = threadIdx.x;
    const int lane = tid & 31;
    const int warp = tid >> 5;
    const int grp  = lane >> 2;
    const int qid  = lane & 3;
    const int wm   = warp * 16;
    const int t0   = blockIdx.x * 128;
    const int n    = blockIdx.y;
    const int b    = blockIdx.z;
    const int kvh  = n >> 2;

    const uint16_t* Qh = qhi + ((size_t)(b * T_ + t0) * NQ  + n)   * HD;
    const uint16_t* Ql = qlo + ((size_t)(b * T_ + t0) * NQ  + n)   * HD;
    const uint16_t* Kh = khi + ((size_t)(b * S_)      * NKV + kvh) * HD;
    const uint16_t* Kl = klo + ((size_t)(b * S_)      * NKV + kvh) * HD;
    const uint16_t* Vf = vf  + ((size_t)(b * S_)      * NKV + kvh) * HD;

    #pragma unroll
    for (int it = 0; it < 16; it++) {
        int f = tid + it * 256;
        int plane = f >> 11;
        int fi = f & 2047;
        int r = fi >> 4, c8 = (fi & 15) << 3;
        const uint16_t* src = (plane ? Ql : Qh) + (size_t)r * (NQ * HD) + c8;
        *(uint4*)(smraw + (plane ? A_QL : A_QH) + ((r * 136 + c8) << 1)) = *(const uint4*)src;
    }

    float m0 = -1e30f, m1 = -1e30f, l0 = 0.f, l1 = 0.f;
    float oacc[16][4];
    #pragma unroll
    for (int j = 0; j < 16; j++)
        #pragma unroll
        for (int c = 0; c < 4; c++) oacc[j][c] = 0.f;

    for (int blk = 0; blk < 32; blk++) {
        __syncthreads();
        {
            const int s0 = blk * 32;
            #pragma unroll
            for (int it = 0; it < 6; it++) {
                int f = tid + it * 256;
                int region = f >> 9;
                int fi = f & 511;
                int r = fi >> 4, c8 = (fi & 15) << 3;
                const uint16_t* src = (region == 0 ? Kh : region == 1 ? Kl : Vf)
                                      + (size_t)(s0 + r) * (NKV * HD) + c8;
                int base = (region == 0) ? A_KH : (region == 1) ? A_KL : A_VS;
                *(uint4*)(smraw + base + ((r * 136 + c8) << 1)) = *(const uint4*)src;
            }
        }
        __syncthreads();

        float sacc[4][4];
        #pragma unroll
        for (int j = 0; j < 4; j++)
            #pragma unroll
            for (int c = 0; c < 4; c++) sacc[j][c] = 0.f;

        #pragma unroll
        for (int kk = 0; kk < 8; kk++) {
            const int col0h = kk * 16;
            uint32_t ah[4], al[4];
            {
                int m = wm + (lane & 15);
                uint32_t ab = sb + A_QH + ((m * 136 + col0h + ((lane >> 4) << 3)) << 1);
                ldsm_x4(ah, ab);
                ldsm_x4(al, ab + (A_QL - A_QH));
            }
            #pragma unroll
            for (int j2 = 0; j2 < 2; j2++) {
                int row = (j2 * 2 + (lane >> 4)) * 8 + (lane & 7);
                uint32_t bb = sb + A_KH + ((row * 136 + col0h + (lane & 8)) << 1);
                uint32_t bh4[4], bl4[4];
                ldsm_x4(bh4, bb);
                ldsm_x4(bl4, bb + (A_KL - A_KH));
                mma_bf16(sacc[2*j2],   ah, bh4);
                mma_bf16(sacc[2*j2],   ah, bl4);
                mma_bf16(sacc[2*j2],   al, bh4);
                mma_bf16(sacc[2*j2+1], ah, bh4 + 2);
                mma_bf16(sacc[2*j2+1], ah, bl4 + 2);
                mma_bf16(sacc[2*j2+1], al, bh4 + 2);
            }
        }

        float mx0 = -1e30f, mx1 = -1e30f;
        #pragma unroll
        for (int j = 0; j < 4; j++) {
            mx0 = fmaxf(mx0, fmaxf(sacc[j][0], sacc[j][1]));
            mx1 = fmaxf(mx1, fmaxf(sacc[j][2], sacc[j][3]));
        }
        #pragma unroll
        for (int off = 1; off < 4; off <<= 1) {
            mx0 = fmaxf(mx0, __shfl_xor_sync(0xffffffffu, mx0, off));
            mx1 = fmaxf(mx1, __shfl_xor_sync(0xffffffffu, mx1, off));
        }
        float mn0 = fmaxf(m0, mx0), mn1 = fmaxf(m1, mx1);
        float cr0 = __expf(m0 - mn0), cr1 = __expf(m1 - mn1);
        float ps0 = 0.f, ps1 = 0.f;
        uint32_t pk[4][2];
        #pragma unroll
        for (int j = 0; j < 4; j++) {
            float e0 = __expf(sacc[j][0] - mn0);
            float e1 = __expf(sacc[j][1] - mn0);
            float e2 = __expf(sacc[j][2] - mn1);
            float e3 = __expf(sacc[j][3] - mn1);
            ps0 += e0 + e1; ps1 += e2 + e3;
            pk[j][0] = fp16_pack2(e0, e1);
            pk[j][1] = fp16_pack2(e2, e3);
        }
        #pragma unroll
        for (int off = 1; off < 4; off <<= 1) {
            ps0 += __shfl_xor_sync(0xffffffffu, ps0, off);
            ps1 += __shfl_xor_sync(0xffffffffu, ps1, off);
        }
        l0 = l0 * cr0 + ps0; m0 = mn0;
        l1 = l1 * cr1 + ps1; m1 = mn1;
        #pragma unroll
        for (int j = 0; j < 16; j++) {
            oacc[j][0] *= cr0; oacc[j][1] *= cr0;
            oacc[j][2] *= cr1; oacc[j][3] *= cr1;
        }

        #pragma unroll
        for (int kk2 = 0; kk2 < 2; kk2++) {
            uint32_t pa[4] = { pk[2*kk2][0], pk[2*kk2][1], pk[2*kk2+1][0], pk[2*kk2+1][1] };
            #pragma unroll
            for (int j2 = 0; j2 < 8; j2++) {
                int kr  = kk2 * 16 + (lane & 15);
                int col = (j2 * 2 + (lane >> 4)) * 8;
                uint32_t vb4[4];
                ldsm_x4t(vb4, sb + A_VS + ((kr * VSH + col) << 1));
                mma_fp16(oacc[2*j2],     pa, vb4);
                mma_fp16(oacc[2*j2 + 1], pa, vb4 + 2);
            }
        }
    }

    float inv0 = 1.0f / l0, inv1 = 1.0f / l1;
    uint16_t* o0 = o + ((size_t)(b * T_ + t0 + wm + grp)     * NQ + n) * HD;
    uint16_t* o1 = o + ((size_t)(b * T_ + t0 + wm + grp + 8) * NQ + n) * HD;
    #pragma unroll
    for (int j = 0; j < 16; j++) {
        int col = j * 8 + 2 * qid;
        *(uint32_t*)(o0 + col) = fp16_pack2(oacc[j][0] * inv0, oacc[j][1] * inv0);
        *(uint32_t*)(o1 + col) = fp16_pack2(oacc[j][2] * inv1, oacc[j][3] * inv1);
    }
}

// ---------------- Launch ----------------
extern "C" void kernel_launch(void* const* d_in, const int* in_sizes, int n_in,
                              void* d_out, int out_size)
{
    const float* Xq  = (const float*)d_in[0];
    const float* Xkv = (const float*)d_in[1];
    const int*   qpos = (const int*)d_in[2];
    const int*   kpos = (const int*)d_in[3];
    const float* Wq  = (const float*)d_in[4];
    const float* Wk  = (const float*)d_in[5];
    const float* Wv  = (const float*)d_in[6];
    const float* Wo  = (const float*)d_in[7];
    float* out = (float*)d_out;

    uint16_t *qh, *ql, *kh, *kl, *vfp, *ah;
    cudaGetSymbolAddress((void**)&qh, g_qhi);
    cudaGetSymbolAddress((void**)&ql, g_qlo);
    cudaGetSymbolAddress((void**)&kh, g_khi);
    cudaGetSymbolAddress((void**)&kl, g_klo);
    cudaGetSymbolAddress((void**)&vfp, g_vf);
    cudaGetSymbolAddress((void**)&ah, g_attn_h);

    const int P_SMEM = 128 * 132 * 4;   // 67584 (epilogue staging; main loop needs 37888)
    const int O_SMEM = 18944;
    cudaFuncSetAttribute(proj_qkv, cudaFuncAttributeMaxDynamicSharedMemorySize, P_SMEM);
    cudaFuncSetAttribute(gemm_o, cudaFuncAttributeMaxDynamicSharedMemorySize, O_SMEM);
    cudaFuncSetAttribute(attn_tc_kernel, cudaFuncAttributeMaxDynamicSharedMemorySize, A_SMEM);

    // Q/K/V projections + fused RoPE/split epilogue (prep kernel eliminated)
    proj_qkv<<<dim3(24, 16), 256, P_SMEM>>>(Xq, Wq, Xkv, Wk, Wv, qpos, kpos,
                                            qh, ql, kh, kl, vfp);

    // Attention (R16-exact)
    attn_tc_kernel<<<dim3(T_/128, NQ, B_), 256, A_SMEM>>>(qh, ql, kh, kl, vfp, ah);

    // Output projection (fp16 A input, occ-2, x4t)
    gemm_o<<<dim3(16, 16), 256, O_SMEM>>>(ah, Wo, out);
}